// round 9
// baseline (speedup 1.0000x reference)
#include <cuda_runtime.h>
#include <cuda_fp16.h>
#include <mma.h>
#include <math.h>

using namespace nvcuda;

#define N_NODES 100000
#define N_EDGES 1600000
#define DIM     128
#define EPSF    1e-12f
#define NBLK    ((N_NODES + 255) / 256)   // 391
#define GTILE   128
#define LDH     136

// block partition for the merged scatter+pack+transpose launch
#define SCAT_BLOCKS 2048
#define PACK_BLOCKS 12500
#define TRAN_BLOCKS 48
#define MERG_BLOCKS (SCAT_BLOCKS + PACK_BLOCKS + TRAN_BLOCKS)

// ---------------- scratch (__device__ globals) -------------------------------
__device__ __align__(16) __half g_pack[(size_t)N_NODES * 384];  // [e|b_tan|s_nrm] fp16
__device__ __align__(16) __half g_emean[(size_t)N_NODES * DIM];
__device__ __align__(16) __half g_bmean[(size_t)N_NODES * DIM];
__device__ __align__(16) __half g_smean[(size_t)N_NODES * DIM];
__device__ __align__(16) __half g_Wth [3 * DIM * DIM];          // W^T fp16
__device__ int   g_counts[N_NODES + NBLK];   // [counts | scan status] one memset
__device__ int   g_rowptr[N_NODES + 1];
__device__ int   g_cursor[N_NODES];
__device__ int   g_csr   [N_EDGES];

// ---------------- helpers ------------------------------------------------------
__device__ __forceinline__ uint2 f4_to_h4(float4 v) {
    __half2 lo = __floats2half2_rn(v.x, v.y);
    __half2 hi = __floats2half2_rn(v.z, v.w);
    uint2 r;
    r.x = *(unsigned*)&lo;
    r.y = *(unsigned*)&hi;
    return r;
}

__device__ __forceinline__ void h4_acc(uint2 u, float4& a) {
    float2 lo = __half22float2(*(__half2*)&u.x);
    float2 hi = __half22float2(*(__half2*)&u.y);
    a.x += lo.x; a.y += lo.y; a.z += hi.x; a.w += hi.y;
}

// fp16 pairwise add (2x HADD2)
__device__ __forceinline__ uint2 h4_add(uint2 a, uint2 b) {
    __half2 ax = *(__half2*)&a.x, ay = *(__half2*)&a.y;
    __half2 bx = *(__half2*)&b.x, by = *(__half2*)&b.y;
    __half2 rx = __hadd2(ax, bx), ry = __hadd2(ay, by);
    uint2 r;
    r.x = *(unsigned*)&rx;
    r.y = *(unsigned*)&ry;
    return r;
}

// ---------------- hist ----------------------------------------------------------
__global__ void hist_kernel(const int* __restrict__ dst, int* __restrict__ counts) {
    int i = blockIdx.x * blockDim.x + threadIdx.x;
    int stride = gridDim.x * blockDim.x;
    for (int e = i; e < N_EDGES; e += stride)
        atomicAdd(counts + __ldg(dst + e), 1);
}

// ---------------- single-kernel decoupled-lookback scan -------------------------
__global__ void __launch_bounds__(256)
scan_lookback(const int* __restrict__ counts, int* __restrict__ rowptr,
              int* __restrict__ cursor, volatile int* status) {
    int b = blockIdx.x, t = threadIdx.x;
    int gid = b * 256 + t;
    int lane = t & 31, wid = t >> 5;
    int v = (gid < N_NODES) ? counts[gid] : 0;

    int x = v;
    #pragma unroll
    for (int o = 1; o < 32; o <<= 1) {
        int y = __shfl_up_sync(0xffffffffu, x, o);
        if (lane >= o) x += y;
    }
    __shared__ int wt[8];
    __shared__ int woff[8];
    __shared__ int s_prefix;
    __shared__ int s_total;
    if (lane == 31) wt[wid] = x;
    __syncthreads();

    if (t == 0) {
        int run = 0;
        #pragma unroll
        for (int i = 0; i < 8; i++) { woff[i] = run; run += wt[i]; }
        s_total = run;
        if (b == 0) {
            status[0] = (run << 2) | 2;
            s_prefix = 0;
        } else {
            status[b] = (run << 2) | 1;
            int running = 0;
            for (int p = b - 1; p >= 0;) {
                int s;
                do { s = status[p]; } while ((s & 3) == 0);
                running += (s >> 2);
                if ((s & 3) == 2) break;
                p--;
            }
            s_prefix = running;
            status[b] = ((running + run) << 2) | 2;
        }
    }
    __syncthreads();

    int ex = x - v + woff[wid] + s_prefix;
    if (gid < N_NODES) { rowptr[gid] = ex; cursor[gid] = ex; }
    if (t == 0 && b == NBLK - 1) rowptr[N_NODES] = s_prefix + s_total;
}

// ---------------- merged: scatter + pack + W transposes -------------------------
__global__ void __launch_bounds__(256)
scatter_pack_kernel(const int* __restrict__ src, const int* __restrict__ dst,
                    int* __restrict__ cursor, int* __restrict__ csr,
                    const float* __restrict__ e_emb, const float* __restrict__ b_emb,
                    const float* __restrict__ s_emb, __half* __restrict__ pack,
                    const float* __restrict__ W0, const float* __restrict__ W1,
                    const float* __restrict__ W2, __half* __restrict__ Wt) {
    int blk = blockIdx.x;

    if (blk < SCAT_BLOCKS) {
        int i = blk * 256 + threadIdx.x;
        int stride = SCAT_BLOCKS * 256;
        for (int e = i; e < N_EDGES; e += stride) {
            int d = __ldg(dst + e);
            int p = atomicAdd(cursor + d, 1);
            csr[p] = __ldg(src + e);
        }
    } else if (blk < SCAT_BLOCKS + PACK_BLOCKS) {
        int lane = threadIdx.x & 31;
        int node = ((blk - SCAT_BLOCKS) * 256 + (int)threadIdx.x) >> 5;
        if (node >= N_NODES) return;

        float4 e = __ldg((const float4*)e_emb + (size_t)node * 32 + lane);
        float4 b = __ldg((const float4*)b_emb + (size_t)node * 32 + lane);
        float4 s = __ldg((const float4*)s_emb + (size_t)node * 32 + lane);

        float nb = b.x*b.x + b.y*b.y + b.z*b.z + b.w*b.w;
        float ns = s.x*s.x + s.y*s.y + s.z*s.z + s.w*s.w;
        #pragma unroll
        for (int o = 16; o; o >>= 1) {
            nb += __shfl_xor_sync(0xffffffffu, nb, o);
            ns += __shfl_xor_sync(0xffffffffu, ns, o);
        }
        float bn_safe = fmaxf(sqrtf(nb), EPSF);
        float bn_cl   = fminf(bn_safe, 1.f - 1e-5f);
        float bsc = atanhf(bn_cl) / bn_safe;
        float ssc = 1.f / fmaxf(sqrtf(ns), EPSF);

        b.x *= bsc; b.y *= bsc; b.z *= bsc; b.w *= bsc;
        s.x *= ssc; s.y *= ssc; s.z *= ssc; s.w *= ssc;

        uint2* row = (uint2*)(pack + (size_t)node * 384);
        row[lane]      = f4_to_h4(e);
        row[32 + lane] = f4_to_h4(b);
        row[64 + lane] = f4_to_h4(s);
    } else {
        __shared__ float t[32][33];
        int tb = blk - SCAT_BLOCKS - PACK_BLOCKS;  // 0..47
        int z = tb >> 4;
        int tile = tb & 15;
        const float* W = (z == 0) ? W0 : (z == 1) ? W1 : W2;
        __half* D = Wt + z * DIM * DIM;
        int bx = (tile & 3) * 32, by = (tile >> 2) * 32;
        int x = threadIdx.x & 31, y = threadIdx.x >> 5;   // (32, 8)
        #pragma unroll
        for (int j = 0; j < 32; j += 8)
            t[y + j][x] = W[(by + y + j) * DIM + bx + x];
        __syncthreads();
        #pragma unroll
        for (int j = 0; j < 32; j += 8)
            D[(bx + y + j) * DIM + by + x] = __float2half(t[x][y + j]);
    }
}

// ---------------- CSR mean-aggregate: warp = (node, space) ---------------------
// 3x more warps, 3x smaller quanta -> balance + occupancy; 1 load/lane/edge.
__global__ void __launch_bounds__(128)
agg_fused(const __half* __restrict__ pack,
          __half* __restrict__ em, __half* __restrict__ bm, __half* __restrict__ sm,
          const int* __restrict__ csr, const int* __restrict__ rp) {
    int lane = threadIdx.x & 31;
    int gw = (blockIdx.x * blockDim.x + threadIdx.x) >> 5;
    if (gw >= 3 * N_NODES) return;
    int space = gw % 3;          // 3 warps of one node adjacent -> shared csr/pack lines
    int node  = gw / 3;

    int beg = __ldg(rp + node), end = __ldg(rp + node + 1);
    const uint2* p2 = (const uint2*)pack + space * 32 + lane;  // lane's slot in space-row
    float4 acc = make_float4(0.f, 0.f, 0.f, 0.f);

    for (int base = beg; base < end; base += 32) {
        int n = min(32, end - base);
        int sidx = (base + lane < end) ? __ldg(csr + base + lane) : 0;
        int j = 0;
        for (; j + 4 <= n; j += 4) {
            int s0 = __shfl_sync(0xffffffffu, sidx, j);
            int s1 = __shfl_sync(0xffffffffu, sidx, j + 1);
            int s2 = __shfl_sync(0xffffffffu, sidx, j + 2);
            int s3 = __shfl_sync(0xffffffffu, sidx, j + 3);
            uint2 v0 = __ldg(p2 + (size_t)s0 * 96);
            uint2 v1 = __ldg(p2 + (size_t)s1 * 96);
            uint2 v2 = __ldg(p2 + (size_t)s2 * 96);
            uint2 v3 = __ldg(p2 + (size_t)s3 * 96);
            h4_acc(h4_add(v0, v1), acc);
            h4_acc(h4_add(v2, v3), acc);
        }
        for (; j < n; j++) {
            int s0 = __shfl_sync(0xffffffffu, sidx, j);
            h4_acc(__ldg(p2 + (size_t)s0 * 96), acc);
        }
    }

    int deg = end - beg;
    float inv = (deg > 0) ? (1.f / (float)deg) : 0.f;
    acc.x *= inv; acc.y *= inv; acc.z *= inv; acc.w *= inv;

    __half* out = (space == 0) ? em : (space == 1) ? bm : sm;
    ((uint2*)out)[(size_t)node * 32 + lane] = f4_to_h4(acc);
}

// ---------------- WMMA GEMM (all 3 spaces in one launch, z = space) ------------
__global__ void __launch_bounds__(256)
gemm_wmma3(const __half* __restrict__ em, const __half* __restrict__ bm,
           const __half* __restrict__ sm, const __half* __restrict__ Wth,
           const float* __restrict__ b_e, const float* __restrict__ b_b,
           const float* __restrict__ b_s, float* __restrict__ out,
           const int* __restrict__ rp) {
    extern __shared__ char sh[];
    __half* Xs = (__half*)sh;                       // [128][136]
    __half* Ws = (__half*)(sh + GTILE * LDH * 2);   // [128][136]
    float*  Os = (float*)sh;                        // [128][128] aliases Xs/Ws

    int z = blockIdx.z;
    const __half* X    = (z == 0) ? em : (z == 1) ? bm : sm;
    const __half* Wt   = Wth + z * DIM * DIM;
    const float*  bias = (z == 0) ? b_e : (z == 1) ? b_b : b_s;
    float*        Y    = out + (size_t)z * N_NODES * DIM;

    int tid = threadIdx.x;
    int warp = tid >> 5, lane = tid & 31;
    int row0 = blockIdx.x * GTILE;

    const uint2* X2 = (const uint2*)X;
    #pragma unroll
    for (int i = 0; i < 16; i++) {
        int f = tid + 256 * i;
        int r = f >> 5, c4 = f & 31;
        int gr = row0 + r;
        uint2 v = make_uint2(0u, 0u);
        if (gr < N_NODES) v = __ldg(X2 + (size_t)gr * 32 + c4);
        *(uint2*)(Xs + r * LDH + c4 * 4) = v;
    }
    const uint2* W2 = (const uint2*)Wt;
    #pragma unroll
    for (int i = 0; i < 16; i++) {
        int f = tid + 256 * i;
        int r = f >> 5, c4 = f & 31;
        *(uint2*)(Ws + r * LDH + c4 * 4) = __ldg(W2 + f);
    }
    __syncthreads();

    wmma::fragment<wmma::accumulator, 16, 16, 16, float> acc[8];
    #pragma unroll
    for (int n = 0; n < 8; n++) wmma::fill_fragment(acc[n], 0.f);

    #pragma unroll
    for (int k = 0; k < 8; k++) {
        wmma::fragment<wmma::matrix_a, 16, 16, 16, __half, wmma::row_major> a;
        wmma::load_matrix_sync(a, Xs + (warp * 16) * LDH + k * 16, LDH);
        #pragma unroll
        for (int n = 0; n < 8; n++) {
            wmma::fragment<wmma::matrix_b, 16, 16, 16, __half, wmma::row_major> b;
            wmma::load_matrix_sync(b, Ws + (k * 16) * LDH + n * 16, LDH);
            wmma::mma_sync(acc[n], a, b, acc[n]);
        }
    }
    __syncthreads();

    #pragma unroll
    for (int n = 0; n < 8; n++)
        wmma::store_matrix_sync(Os + (warp * 16) * GTILE + n * 16, acc[n], GTILE,
                                wmma::mem_row_major);
    __syncthreads();

    float4 bv = __ldg((const float4*)bias + lane);
    #pragma unroll
    for (int i = 0; i < 16; i++) {
        int r = warp * 16 + i;
        int gr = row0 + r;
        if (gr >= N_NODES) break;
        float4 v = *(const float4*)(Os + r * GTILE + lane * 4);
        v.x += bv.x; v.y += bv.y; v.z += bv.z; v.w += bv.w;
        if (z == 0) {
            v.x = (v.x >= 0.f) ? v.x : 0.2f * v.x;
            v.y = (v.y >= 0.f) ? v.y : 0.2f * v.y;
            v.z = (v.z >= 0.f) ? v.z : 0.2f * v.z;
            v.w = (v.w >= 0.f) ? v.w : 0.2f * v.w;
        } else {
            int deg = __ldg(rp + gr + 1) - __ldg(rp + gr);
            if (deg == 0) {
                v = make_float4(0.f, 0.f, 0.f, 0.f);
            } else {
                float ss = v.x*v.x + v.y*v.y + v.z*v.z + v.w*v.w;
                #pragma unroll
                for (int o = 16; o; o >>= 1) ss += __shfl_xor_sync(0xffffffffu, ss, o);
                float ns = fmaxf(sqrtf(ss), EPSF);
                float sc = (z == 1) ? (tanhf(ns) / ns) : (1.f / ns);
                v.x *= sc; v.y *= sc; v.z *= sc; v.w *= sc;
            }
        }
        ((float4*)Y)[(size_t)gr * 32 + lane] = v;
    }
}

// ---------------- launch --------------------------------------------------------
extern "C" void kernel_launch(void* const* d_in, const int* in_sizes, int n_in,
                              void* d_out, int out_size) {
    const float* e_emb = (const float*)d_in[0];
    const float* b_emb = (const float*)d_in[1];
    const float* s_emb = (const float*)d_in[2];
    const float* W_e   = (const float*)d_in[3];
    const float* b_e   = (const float*)d_in[4];
    const float* W_b   = (const float*)d_in[5];
    const float* b_b   = (const float*)d_in[6];
    const float* W_s   = (const float*)d_in[7];
    const float* b_s   = (const float*)d_in[8];
    const int*   src   = (const int*)d_in[9];
    const int*   dst   = (const int*)d_in[10];

    float* out = (float*)d_out;

    __half *pack, *emean, *bmean, *smean, *Wth;
    int *counts, *rowptr, *cursor, *csr;
    cudaGetSymbolAddress((void**)&pack,   g_pack);
    cudaGetSymbolAddress((void**)&emean,  g_emean);
    cudaGetSymbolAddress((void**)&bmean,  g_bmean);
    cudaGetSymbolAddress((void**)&smean,  g_smean);
    cudaGetSymbolAddress((void**)&Wth,    g_Wth);
    cudaGetSymbolAddress((void**)&counts, g_counts);
    cudaGetSymbolAddress((void**)&rowptr, g_rowptr);
    cudaGetSymbolAddress((void**)&cursor, g_cursor);
    cudaGetSymbolAddress((void**)&csr,    g_csr);
    int* status = counts + N_NODES;

    const int GSMEM = 2 * GTILE * LDH * 2;   // 69632 B
    cudaFuncSetAttribute(gemm_wmma3, cudaFuncAttributeMaxDynamicSharedMemorySize, GSMEM);

    cudaMemsetAsync(counts, 0, (N_NODES + NBLK) * sizeof(int));
    hist_kernel<<<2048, 256>>>(dst, counts);
    scan_lookback<<<NBLK, 256>>>(counts, rowptr, cursor, status);
    scatter_pack_kernel<<<MERG_BLOCKS, 256>>>(src, dst, cursor, csr,
                                              e_emb, b_emb, s_emb, pack,
                                              W_e, W_b, W_s, Wth);

    // warp = (node, space): 300k warps, 128-thread blocks
    const long long AGG_WARPS = 3LL * N_NODES;
    const int AGG_BLOCKS = (int)((AGG_WARPS * 32 + 127) / 128);   // 75000
    agg_fused<<<AGG_BLOCKS, 128>>>(pack, emean, bmean, smean, csr, rowptr);

    dim3 gg((N_NODES + GTILE - 1) / GTILE, 1, 3);   // 782 x 1 x 3
    gemm_wmma3<<<gg, 256, GSMEM>>>(emean, bmean, smean, Wth, b_e, b_b, b_s, out, rowptr);
}

// round 10
// speedup vs baseline: 1.0479x; 1.0479x over previous
#include <cuda_runtime.h>
#include <cuda_fp16.h>
#include <mma.h>
#include <math.h>

using namespace nvcuda;

#define N_NODES 100000
#define N_EDGES 1600000
#define DIM     128
#define EPSF    1e-12f
#define NBLK    ((N_NODES + 255) / 256)   // 391
#define GTILE   128
#define LDH     136

// block partition for the merged scatter+pack+transpose launch
#define SCAT_BLOCKS 2048
#define PACK_BLOCKS 12500
#define TRAN_BLOCKS 48
#define MERG_BLOCKS (SCAT_BLOCKS + PACK_BLOCKS + TRAN_BLOCKS)

// ---------------- scratch (__device__ globals) -------------------------------
__device__ __align__(16) __half g_pack[(size_t)N_NODES * 384];  // [e|b_tan|s_nrm] fp16
__device__ __align__(16) __half g_emean[(size_t)N_NODES * DIM];
__device__ __align__(16) __half g_bmean[(size_t)N_NODES * DIM];
__device__ __align__(16) __half g_smean[(size_t)N_NODES * DIM];
__device__ __align__(16) __half g_Wth [3 * DIM * DIM];          // W^T fp16
__device__ int   g_counts[N_NODES + NBLK];   // [counts | scan status] one memset
__device__ int   g_rowptr[N_NODES + 1];
__device__ int   g_cursor[N_NODES];
__device__ int   g_csr   [N_EDGES];

// ---------------- helpers ------------------------------------------------------
__device__ __forceinline__ uint2 f4_to_h4(float4 v) {
    __half2 lo = __floats2half2_rn(v.x, v.y);
    __half2 hi = __floats2half2_rn(v.z, v.w);
    uint2 r;
    r.x = *(unsigned*)&lo;
    r.y = *(unsigned*)&hi;
    return r;
}

__device__ __forceinline__ void h4_acc(uint2 u, float4& a) {
    float2 lo = __half22float2(*(__half2*)&u.x);
    float2 hi = __half22float2(*(__half2*)&u.y);
    a.x += lo.x; a.y += lo.y; a.z += hi.x; a.w += hi.y;
}

// fp16 pairwise add (2x HADD2)
__device__ __forceinline__ uint2 h4_add(uint2 a, uint2 b) {
    __half2 ax = *(__half2*)&a.x, ay = *(__half2*)&a.y;
    __half2 bx = *(__half2*)&b.x, by = *(__half2*)&b.y;
    __half2 rx = __hadd2(ax, bx), ry = __hadd2(ay, by);
    uint2 r;
    r.x = *(unsigned*)&rx;
    r.y = *(unsigned*)&ry;
    return r;
}

// ---------------- hist ----------------------------------------------------------
__global__ void hist_kernel(const int* __restrict__ dst, int* __restrict__ counts) {
    int i = blockIdx.x * blockDim.x + threadIdx.x;
    int stride = gridDim.x * blockDim.x;
    for (int e = i; e < N_EDGES; e += stride)
        atomicAdd(counts + __ldg(dst + e), 1);
}

// ---------------- single-kernel decoupled-lookback scan -------------------------
__global__ void __launch_bounds__(256)
scan_lookback(const int* __restrict__ counts, int* __restrict__ rowptr,
              int* __restrict__ cursor, volatile int* status) {
    int b = blockIdx.x, t = threadIdx.x;
    int gid = b * 256 + t;
    int lane = t & 31, wid = t >> 5;
    int v = (gid < N_NODES) ? counts[gid] : 0;

    int x = v;
    #pragma unroll
    for (int o = 1; o < 32; o <<= 1) {
        int y = __shfl_up_sync(0xffffffffu, x, o);
        if (lane >= o) x += y;
    }
    __shared__ int wt[8];
    __shared__ int woff[8];
    __shared__ int s_prefix;
    __shared__ int s_total;
    if (lane == 31) wt[wid] = x;
    __syncthreads();

    if (t == 0) {
        int run = 0;
        #pragma unroll
        for (int i = 0; i < 8; i++) { woff[i] = run; run += wt[i]; }
        s_total = run;
        if (b == 0) {
            status[0] = (run << 2) | 2;
            s_prefix = 0;
        } else {
            status[b] = (run << 2) | 1;
            int running = 0;
            for (int p = b - 1; p >= 0;) {
                int s;
                do { s = status[p]; } while ((s & 3) == 0);
                running += (s >> 2);
                if ((s & 3) == 2) break;
                p--;
            }
            s_prefix = running;
            status[b] = ((running + run) << 2) | 2;
        }
    }
    __syncthreads();

    int ex = x - v + woff[wid] + s_prefix;
    if (gid < N_NODES) { rowptr[gid] = ex; cursor[gid] = ex; }
    if (t == 0 && b == NBLK - 1) rowptr[N_NODES] = s_prefix + s_total;
}

// ---------------- merged: scatter + pack + W transposes -------------------------
__global__ void __launch_bounds__(256)
scatter_pack_kernel(const int* __restrict__ src, const int* __restrict__ dst,
                    int* __restrict__ cursor, int* __restrict__ csr,
                    const float* __restrict__ e_emb, const float* __restrict__ b_emb,
                    const float* __restrict__ s_emb, __half* __restrict__ pack,
                    const float* __restrict__ W0, const float* __restrict__ W1,
                    const float* __restrict__ W2, __half* __restrict__ Wt) {
    int blk = blockIdx.x;

    if (blk < SCAT_BLOCKS) {
        int i = blk * 256 + threadIdx.x;
        int stride = SCAT_BLOCKS * 256;
        for (int e = i; e < N_EDGES; e += stride) {
            int d = __ldg(dst + e);
            int p = atomicAdd(cursor + d, 1);
            csr[p] = __ldg(src + e);
        }
    } else if (blk < SCAT_BLOCKS + PACK_BLOCKS) {
        int lane = threadIdx.x & 31;
        int node = ((blk - SCAT_BLOCKS) * 256 + (int)threadIdx.x) >> 5;
        if (node >= N_NODES) return;

        float4 e = __ldg((const float4*)e_emb + (size_t)node * 32 + lane);
        float4 b = __ldg((const float4*)b_emb + (size_t)node * 32 + lane);
        float4 s = __ldg((const float4*)s_emb + (size_t)node * 32 + lane);

        float nb = b.x*b.x + b.y*b.y + b.z*b.z + b.w*b.w;
        float ns = s.x*s.x + s.y*s.y + s.z*s.z + s.w*s.w;
        #pragma unroll
        for (int o = 16; o; o >>= 1) {
            nb += __shfl_xor_sync(0xffffffffu, nb, o);
            ns += __shfl_xor_sync(0xffffffffu, ns, o);
        }
        float bn_safe = fmaxf(sqrtf(nb), EPSF);
        float bn_cl   = fminf(bn_safe, 1.f - 1e-5f);
        float bsc = atanhf(bn_cl) / bn_safe;
        float ssc = 1.f / fmaxf(sqrtf(ns), EPSF);

        b.x *= bsc; b.y *= bsc; b.z *= bsc; b.w *= bsc;
        s.x *= ssc; s.y *= ssc; s.z *= ssc; s.w *= ssc;

        uint2* row = (uint2*)(pack + (size_t)node * 384);
        row[lane]      = f4_to_h4(e);
        row[32 + lane] = f4_to_h4(b);
        row[64 + lane] = f4_to_h4(s);
    } else {
        __shared__ float t[32][33];
        int tb = blk - SCAT_BLOCKS - PACK_BLOCKS;  // 0..47
        int z = tb >> 4;
        int tile = tb & 15;
        const float* W = (z == 0) ? W0 : (z == 1) ? W1 : W2;
        __half* D = Wt + z * DIM * DIM;
        int bx = (tile & 3) * 32, by = (tile >> 2) * 32;
        int x = threadIdx.x & 31, y = threadIdx.x >> 5;   // (32, 8)
        #pragma unroll
        for (int j = 0; j < 32; j += 8)
            t[y + j][x] = W[(by + y + j) * DIM + bx + x];
        __syncthreads();
        #pragma unroll
        for (int j = 0; j < 32; j += 8)
            D[(bx + y + j) * DIM + by + x] = __float2half(t[x][y + j]);
    }
}

// ---------------- fused CSR mean-aggregate (fp16 out), warp per node -----------
// unroll x2 + HADD2 pairing: per-warp MLP already beyond LSU cap, so keep
// registers low (occupancy) rather than loads-in-flight high.
__global__ void agg_fused(const __half* __restrict__ pack,
                          __half* __restrict__ em, __half* __restrict__ bm, __half* __restrict__ sm,
                          const int* __restrict__ csr, const int* __restrict__ rp) {
    int lane = threadIdx.x & 31;
    int node = (blockIdx.x * blockDim.x + threadIdx.x) >> 5;
    if (node >= N_NODES) return;

    int beg = __ldg(rp + node), end = __ldg(rp + node + 1);
    float4 ae = make_float4(0,0,0,0), ab = make_float4(0,0,0,0), as = make_float4(0,0,0,0);
    const uint2* p2 = (const uint2*)pack;

    for (int base = beg; base < end; base += 32) {
        int n = min(32, end - base);
        int sidx = (base + lane < end) ? __ldg(csr + base + lane) : 0;
        int j = 0;
        for (; j + 2 <= n; j += 2) {
            int s0 = __shfl_sync(0xffffffffu, sidx, j);
            int s1 = __shfl_sync(0xffffffffu, sidx, j + 1);
            const uint2* r0 = p2 + (size_t)s0 * 96;
            const uint2* r1 = p2 + (size_t)s1 * 96;
            uint2 e0 = __ldg(r0 + lane),      e1 = __ldg(r1 + lane);
            uint2 b0 = __ldg(r0 + 32 + lane), b1 = __ldg(r1 + 32 + lane);
            uint2 c0 = __ldg(r0 + 64 + lane), c1 = __ldg(r1 + 64 + lane);
            h4_acc(h4_add(e0, e1), ae);
            h4_acc(h4_add(b0, b1), ab);
            h4_acc(h4_add(c0, c1), as);
        }
        for (; j < n; j++) {
            int s0 = __shfl_sync(0xffffffffu, sidx, j);
            const uint2* r0 = p2 + (size_t)s0 * 96;
            h4_acc(__ldg(r0 + lane), ae);
            h4_acc(__ldg(r0 + 32 + lane), ab);
            h4_acc(__ldg(r0 + 64 + lane), as);
        }
    }

    int deg = end - beg;
    float inv = (deg > 0) ? (1.f / (float)deg) : 0.f;
    ae.x *= inv; ae.y *= inv; ae.z *= inv; ae.w *= inv;
    ab.x *= inv; ab.y *= inv; ab.z *= inv; ab.w *= inv;
    as.x *= inv; as.y *= inv; as.z *= inv; as.w *= inv;

    size_t o = (size_t)node * 32 + lane;
    ((uint2*)em)[o] = f4_to_h4(ae);
    ((uint2*)bm)[o] = f4_to_h4(ab);
    ((uint2*)sm)[o] = f4_to_h4(as);
}

// ---------------- WMMA GEMM (all 3 spaces in one launch, z = space) ------------
__global__ void __launch_bounds__(256)
gemm_wmma3(const __half* __restrict__ em, const __half* __restrict__ bm,
           const __half* __restrict__ sm, const __half* __restrict__ Wth,
           const float* __restrict__ b_e, const float* __restrict__ b_b,
           const float* __restrict__ b_s, float* __restrict__ out,
           const int* __restrict__ rp) {
    extern __shared__ char sh[];
    __half* Xs = (__half*)sh;                       // [128][136]
    __half* Ws = (__half*)(sh + GTILE * LDH * 2);   // [128][136]
    float*  Os = (float*)sh;                        // [128][128] aliases Xs/Ws

    int z = blockIdx.z;
    const __half* X    = (z == 0) ? em : (z == 1) ? bm : sm;
    const __half* Wt   = Wth + z * DIM * DIM;
    const float*  bias = (z == 0) ? b_e : (z == 1) ? b_b : b_s;
    float*        Y    = out + (size_t)z * N_NODES * DIM;

    int tid = threadIdx.x;
    int warp = tid >> 5, lane = tid & 31;
    int row0 = blockIdx.x * GTILE;

    const uint2* X2 = (const uint2*)X;
    #pragma unroll
    for (int i = 0; i < 16; i++) {
        int f = tid + 256 * i;
        int r = f >> 5, c4 = f & 31;
        int gr = row0 + r;
        uint2 v = make_uint2(0u, 0u);
        if (gr < N_NODES) v = __ldg(X2 + (size_t)gr * 32 + c4);
        *(uint2*)(Xs + r * LDH + c4 * 4) = v;
    }
    const uint2* W2 = (const uint2*)Wt;
    #pragma unroll
    for (int i = 0; i < 16; i++) {
        int f = tid + 256 * i;
        int r = f >> 5, c4 = f & 31;
        *(uint2*)(Ws + r * LDH + c4 * 4) = __ldg(W2 + f);
    }
    __syncthreads();

    wmma::fragment<wmma::accumulator, 16, 16, 16, float> acc[8];
    #pragma unroll
    for (int n = 0; n < 8; n++) wmma::fill_fragment(acc[n], 0.f);

    #pragma unroll
    for (int k = 0; k < 8; k++) {
        wmma::fragment<wmma::matrix_a, 16, 16, 16, __half, wmma::row_major> a;
        wmma::load_matrix_sync(a, Xs + (warp * 16) * LDH + k * 16, LDH);
        #pragma unroll
        for (int n = 0; n < 8; n++) {
            wmma::fragment<wmma::matrix_b, 16, 16, 16, __half, wmma::row_major> b;
            wmma::load_matrix_sync(b, Ws + (k * 16) * LDH + n * 16, LDH);
            wmma::mma_sync(acc[n], a, b, acc[n]);
        }
    }
    __syncthreads();

    #pragma unroll
    for (int n = 0; n < 8; n++)
        wmma::store_matrix_sync(Os + (warp * 16) * GTILE + n * 16, acc[n], GTILE,
                                wmma::mem_row_major);
    __syncthreads();

    float4 bv = __ldg((const float4*)bias + lane);
    #pragma unroll
    for (int i = 0; i < 16; i++) {
        int r = warp * 16 + i;
        int gr = row0 + r;
        if (gr >= N_NODES) break;
        float4 v = *(const float4*)(Os + r * GTILE + lane * 4);
        v.x += bv.x; v.y += bv.y; v.z += bv.z; v.w += bv.w;
        if (z == 0) {
            v.x = (v.x >= 0.f) ? v.x : 0.2f * v.x;
            v.y = (v.y >= 0.f) ? v.y : 0.2f * v.y;
            v.z = (v.z >= 0.f) ? v.z : 0.2f * v.z;
            v.w = (v.w >= 0.f) ? v.w : 0.2f * v.w;
        } else {
            int deg = __ldg(rp + gr + 1) - __ldg(rp + gr);
            if (deg == 0) {
                v = make_float4(0.f, 0.f, 0.f, 0.f);
            } else {
                float ss = v.x*v.x + v.y*v.y + v.z*v.z + v.w*v.w;
                #pragma unroll
                for (int o = 16; o; o >>= 1) ss += __shfl_xor_sync(0xffffffffu, ss, o);
                float ns = fmaxf(sqrtf(ss), EPSF);
                float sc = (z == 1) ? (tanhf(ns) / ns) : (1.f / ns);
                v.x *= sc; v.y *= sc; v.z *= sc; v.w *= sc;
            }
        }
        ((float4*)Y)[(size_t)gr * 32 + lane] = v;
    }
}

// ---------------- launch --------------------------------------------------------
extern "C" void kernel_launch(void* const* d_in, const int* in_sizes, int n_in,
                              void* d_out, int out_size) {
    const float* e_emb = (const float*)d_in[0];
    const float* b_emb = (const float*)d_in[1];
    const float* s_emb = (const float*)d_in[2];
    const float* W_e   = (const float*)d_in[3];
    const float* b_e   = (const float*)d_in[4];
    const float* W_b   = (const float*)d_in[5];
    const float* b_b   = (const float*)d_in[6];
    const float* W_s   = (const float*)d_in[7];
    const float* b_s   = (const float*)d_in[8];
    const int*   src   = (const int*)d_in[9];
    const int*   dst   = (const int*)d_in[10];

    float* out = (float*)d_out;

    __half *pack, *emean, *bmean, *smean, *Wth;
    int *counts, *rowptr, *cursor, *csr;
    cudaGetSymbolAddress((void**)&pack,   g_pack);
    cudaGetSymbolAddress((void**)&emean,  g_emean);
    cudaGetSymbolAddress((void**)&bmean,  g_bmean);
    cudaGetSymbolAddress((void**)&smean,  g_smean);
    cudaGetSymbolAddress((void**)&Wth,    g_Wth);
    cudaGetSymbolAddress((void**)&counts, g_counts);
    cudaGetSymbolAddress((void**)&rowptr, g_rowptr);
    cudaGetSymbolAddress((void**)&cursor, g_cursor);
    cudaGetSymbolAddress((void**)&csr,    g_csr);
    int* status = counts + N_NODES;

    const int GSMEM = 2 * GTILE * LDH * 2;   // 69632 B
    cudaFuncSetAttribute(gemm_wmma3, cudaFuncAttributeMaxDynamicSharedMemorySize, GSMEM);

    cudaMemsetAsync(counts, 0, (N_NODES + NBLK) * sizeof(int));
    hist_kernel<<<2048, 256>>>(dst, counts);
    scan_lookback<<<NBLK, 256>>>(counts, rowptr, cursor, status);
    scatter_pack_kernel<<<MERG_BLOCKS, 256>>>(src, dst, cursor, csr,
                                              e_emb, b_emb, s_emb, pack,
                                              W_e, W_b, W_s, Wth);
    agg_fused<<<(N_NODES * 32 + 255) / 256, 256>>>(pack, emean, bmean, smean, csr, rowptr);

    dim3 gg((N_NODES + GTILE - 1) / GTILE, 1, 3);   // 782 x 1 x 3
    gemm_wmma3<<<gg, 256, GSMEM>>>(emean, bmean, smean, Wth, b_e, b_b, b_s, out, rowptr);
}

// round 11
// speedup vs baseline: 1.1311x; 1.0794x over previous
#include <cuda_runtime.h>
#include <cuda_fp16.h>
#include <mma.h>
#include <math.h>

using namespace nvcuda;

#define N_NODES 100000
#define N_EDGES 1600000
#define DIM     128
#define EPSF    1e-12f
#define NBLK    ((N_NODES + 255) / 256)   // 391
#define GTILE   128
#define LDH     136

// block partition for the merged scatter+pack+transpose launch
#define SCAT_BLOCKS 2048
#define PACK_BLOCKS 12500
#define TRAN_BLOCKS 48
#define MERG_BLOCKS (SCAT_BLOCKS + PACK_BLOCKS + TRAN_BLOCKS)

// ---------------- scratch (__device__ globals) -------------------------------
__device__ __align__(16) __half g_pack[(size_t)N_NODES * 384];  // [e|b_tan|s_nrm] fp16
__device__ __align__(16) __half g_emean[(size_t)N_NODES * DIM];
__device__ __align__(16) __half g_bmean[(size_t)N_NODES * DIM];
__device__ __align__(16) __half g_smean[(size_t)N_NODES * DIM];
__device__ __align__(16) __half g_Wth [3 * DIM * DIM];          // W^T fp16
__device__ int   g_counts[N_NODES + NBLK];   // [counts | scan status] one memset
__device__ int   g_rowptr[N_NODES + 1];
__device__ int   g_cursor[N_NODES];
__device__ int   g_csr   [N_EDGES];

// ---------------- helpers ------------------------------------------------------
__device__ __forceinline__ uint2 f4_to_h4(float4 v) {
    __half2 lo = __floats2half2_rn(v.x, v.y);
    __half2 hi = __floats2half2_rn(v.z, v.w);
    uint2 r;
    r.x = *(unsigned*)&lo;
    r.y = *(unsigned*)&hi;
    return r;
}

__device__ __forceinline__ void h4_acc(uint2 u, float4& a) {
    float2 lo = __half22float2(*(__half2*)&u.x);
    float2 hi = __half22float2(*(__half2*)&u.y);
    a.x += lo.x; a.y += lo.y; a.z += hi.x; a.w += hi.y;
}

// fp16 pairwise add (2x HADD2)
__device__ __forceinline__ uint2 h4_add(uint2 a, uint2 b) {
    __half2 ax = *(__half2*)&a.x, ay = *(__half2*)&a.y;
    __half2 bx = *(__half2*)&b.x, by = *(__half2*)&b.y;
    __half2 rx = __hadd2(ax, bx), ry = __hadd2(ay, by);
    uint2 r;
    r.x = *(unsigned*)&rx;
    r.y = *(unsigned*)&ry;
    return r;
}

// ---------------- hist ----------------------------------------------------------
__global__ void hist_kernel(const int* __restrict__ dst, int* __restrict__ counts) {
    int i = blockIdx.x * blockDim.x + threadIdx.x;
    int stride = gridDim.x * blockDim.x;
    for (int e = i; e < N_EDGES; e += stride)
        atomicAdd(counts + __ldg(dst + e), 1);
}

// ---------------- single-kernel decoupled-lookback scan -------------------------
__global__ void __launch_bounds__(256)
scan_lookback(const int* __restrict__ counts, int* __restrict__ rowptr,
              int* __restrict__ cursor, volatile int* status) {
    int b = blockIdx.x, t = threadIdx.x;
    int gid = b * 256 + t;
    int lane = t & 31, wid = t >> 5;
    int v = (gid < N_NODES) ? counts[gid] : 0;

    int x = v;
    #pragma unroll
    for (int o = 1; o < 32; o <<= 1) {
        int y = __shfl_up_sync(0xffffffffu, x, o);
        if (lane >= o) x += y;
    }
    __shared__ int wt[8];
    __shared__ int woff[8];
    __shared__ int s_prefix;
    __shared__ int s_total;
    if (lane == 31) wt[wid] = x;
    __syncthreads();

    if (t == 0) {
        int run = 0;
        #pragma unroll
        for (int i = 0; i < 8; i++) { woff[i] = run; run += wt[i]; }
        s_total = run;
        if (b == 0) {
            status[0] = (run << 2) | 2;
            s_prefix = 0;
        } else {
            status[b] = (run << 2) | 1;
            int running = 0;
            for (int p = b - 1; p >= 0;) {
                int s;
                do { s = status[p]; } while ((s & 3) == 0);
                running += (s >> 2);
                if ((s & 3) == 2) break;
                p--;
            }
            s_prefix = running;
            status[b] = ((running + run) << 2) | 2;
        }
    }
    __syncthreads();

    int ex = x - v + woff[wid] + s_prefix;
    if (gid < N_NODES) { rowptr[gid] = ex; cursor[gid] = ex; }
    if (t == 0 && b == NBLK - 1) rowptr[N_NODES] = s_prefix + s_total;
}

// ---------------- merged: scatter + pack + W transposes -------------------------
__global__ void __launch_bounds__(256)
scatter_pack_kernel(const int* __restrict__ src, const int* __restrict__ dst,
                    int* __restrict__ cursor, int* __restrict__ csr,
                    const float* __restrict__ e_emb, const float* __restrict__ b_emb,
                    const float* __restrict__ s_emb, __half* __restrict__ pack,
                    const float* __restrict__ W0, const float* __restrict__ W1,
                    const float* __restrict__ W2, __half* __restrict__ Wt) {
    int blk = blockIdx.x;

    if (blk < SCAT_BLOCKS) {
        int i = blk * 256 + threadIdx.x;
        int stride = SCAT_BLOCKS * 256;
        for (int e = i; e < N_EDGES; e += stride) {
            int d = __ldg(dst + e);
            int p = atomicAdd(cursor + d, 1);
            csr[p] = __ldg(src + e);
        }
    } else if (blk < SCAT_BLOCKS + PACK_BLOCKS) {
        int lane = threadIdx.x & 31;
        int node = ((blk - SCAT_BLOCKS) * 256 + (int)threadIdx.x) >> 5;
        if (node >= N_NODES) return;

        float4 e = __ldg((const float4*)e_emb + (size_t)node * 32 + lane);
        float4 b = __ldg((const float4*)b_emb + (size_t)node * 32 + lane);
        float4 s = __ldg((const float4*)s_emb + (size_t)node * 32 + lane);

        float nb = b.x*b.x + b.y*b.y + b.z*b.z + b.w*b.w;
        float ns = s.x*s.x + s.y*s.y + s.z*s.z + s.w*s.w;
        #pragma unroll
        for (int o = 16; o; o >>= 1) {
            nb += __shfl_xor_sync(0xffffffffu, nb, o);
            ns += __shfl_xor_sync(0xffffffffu, ns, o);
        }
        float bn_safe = fmaxf(sqrtf(nb), EPSF);
        float bn_cl   = fminf(bn_safe, 1.f - 1e-5f);
        float bsc = atanhf(bn_cl) / bn_safe;
        float ssc = 1.f / fmaxf(sqrtf(ns), EPSF);

        b.x *= bsc; b.y *= bsc; b.z *= bsc; b.w *= bsc;
        s.x *= ssc; s.y *= ssc; s.z *= ssc; s.w *= ssc;

        uint2* row = (uint2*)(pack + (size_t)node * 384);
        row[lane]      = f4_to_h4(e);
        row[32 + lane] = f4_to_h4(b);
        row[64 + lane] = f4_to_h4(s);
    } else {
        __shared__ float t[32][33];
        int tb = blk - SCAT_BLOCKS - PACK_BLOCKS;  // 0..47
        int z = tb >> 4;
        int tile = tb & 15;
        const float* W = (z == 0) ? W0 : (z == 1) ? W1 : W2;
        __half* D = Wt + z * DIM * DIM;
        int bx = (tile & 3) * 32, by = (tile >> 2) * 32;
        int x = threadIdx.x & 31, y = threadIdx.x >> 5;   // (32, 8)
        #pragma unroll
        for (int j = 0; j < 32; j += 8)
            t[y + j][x] = W[(by + y + j) * DIM + bx + x];
        __syncthreads();
        #pragma unroll
        for (int j = 0; j < 32; j += 8)
            D[(bx + y + j) * DIM + by + x] = __float2half(t[x][y + j]);
    }
}

// ---------------- fused CSR mean-aggregate (fp16 out), warp per node -----------
// x4 edge unroll (12 independent loads in flight = proven MLP sweet spot)
// + 2-level fp16 reduction tree (fewer issue slots per edge).
__global__ void agg_fused(const __half* __restrict__ pack,
                          __half* __restrict__ em, __half* __restrict__ bm, __half* __restrict__ sm,
                          const int* __restrict__ csr, const int* __restrict__ rp) {
    int lane = threadIdx.x & 31;
    int node = (blockIdx.x * blockDim.x + threadIdx.x) >> 5;
    if (node >= N_NODES) return;

    int beg = __ldg(rp + node), end = __ldg(rp + node + 1);
    float4 ae = make_float4(0,0,0,0), ab = make_float4(0,0,0,0), as = make_float4(0,0,0,0);
    const uint2* p2 = (const uint2*)pack;

    for (int base = beg; base < end; base += 32) {
        int n = min(32, end - base);
        int sidx = (base + lane < end) ? __ldg(csr + base + lane) : 0;
        int j = 0;
        for (; j + 4 <= n; j += 4) {
            int s0 = __shfl_sync(0xffffffffu, sidx, j);
            int s1 = __shfl_sync(0xffffffffu, sidx, j + 1);
            int s2 = __shfl_sync(0xffffffffu, sidx, j + 2);
            int s3 = __shfl_sync(0xffffffffu, sidx, j + 3);
            const uint2* r0 = p2 + (size_t)s0 * 96;
            const uint2* r1 = p2 + (size_t)s1 * 96;
            const uint2* r2 = p2 + (size_t)s2 * 96;
            const uint2* r3 = p2 + (size_t)s3 * 96;
            uint2 e0 = __ldg(r0 + lane),      e1 = __ldg(r1 + lane);
            uint2 e2 = __ldg(r2 + lane),      e3 = __ldg(r3 + lane);
            uint2 b0 = __ldg(r0 + 32 + lane), b1 = __ldg(r1 + 32 + lane);
            uint2 b2 = __ldg(r2 + 32 + lane), b3 = __ldg(r3 + 32 + lane);
            uint2 c0 = __ldg(r0 + 64 + lane), c1 = __ldg(r1 + 64 + lane);
            uint2 c2 = __ldg(r2 + 64 + lane), c3 = __ldg(r3 + 64 + lane);
            // 2-level fp16 tree, one fp32 accumulate per 4 edges per space
            h4_acc(h4_add(h4_add(e0, e1), h4_add(e2, e3)), ae);
            h4_acc(h4_add(h4_add(b0, b1), h4_add(b2, b3)), ab);
            h4_acc(h4_add(h4_add(c0, c1), h4_add(c2, c3)), as);
        }
        for (; j < n; j++) {
            int s0 = __shfl_sync(0xffffffffu, sidx, j);
            const uint2* r0 = p2 + (size_t)s0 * 96;
            h4_acc(__ldg(r0 + lane), ae);
            h4_acc(__ldg(r0 + 32 + lane), ab);
            h4_acc(__ldg(r0 + 64 + lane), as);
        }
    }

    int deg = end - beg;
    float inv = (deg > 0) ? (1.f / (float)deg) : 0.f;
    ae.x *= inv; ae.y *= inv; ae.z *= inv; ae.w *= inv;
    ab.x *= inv; ab.y *= inv; ab.z *= inv; ab.w *= inv;
    as.x *= inv; as.y *= inv; as.z *= inv; as.w *= inv;

    size_t o = (size_t)node * 32 + lane;
    ((uint2*)em)[o] = f4_to_h4(ae);
    ((uint2*)bm)[o] = f4_to_h4(ab);
    ((uint2*)sm)[o] = f4_to_h4(as);
}

// ---------------- WMMA GEMM (all 3 spaces in one launch, z = space) ------------
__global__ void __launch_bounds__(256)
gemm_wmma3(const __half* __restrict__ em, const __half* __restrict__ bm,
           const __half* __restrict__ sm, const __half* __restrict__ Wth,
           const float* __restrict__ b_e, const float* __restrict__ b_b,
           const float* __restrict__ b_s, float* __restrict__ out,
           const int* __restrict__ rp) {
    extern __shared__ char sh[];
    __half* Xs = (__half*)sh;                       // [128][136]
    __half* Ws = (__half*)(sh + GTILE * LDH * 2);   // [128][136]
    float*  Os = (float*)sh;                        // [128][128] aliases Xs/Ws

    int z = blockIdx.z;
    const __half* X    = (z == 0) ? em : (z == 1) ? bm : sm;
    const __half* Wt   = Wth + z * DIM * DIM;
    const float*  bias = (z == 0) ? b_e : (z == 1) ? b_b : b_s;
    float*        Y    = out + (size_t)z * N_NODES * DIM;

    int tid = threadIdx.x;
    int warp = tid >> 5, lane = tid & 31;
    int row0 = blockIdx.x * GTILE;

    const uint2* X2 = (const uint2*)X;
    #pragma unroll
    for (int i = 0; i < 16; i++) {
        int f = tid + 256 * i;
        int r = f >> 5, c4 = f & 31;
        int gr = row0 + r;
        uint2 v = make_uint2(0u, 0u);
        if (gr < N_NODES) v = __ldg(X2 + (size_t)gr * 32 + c4);
        *(uint2*)(Xs + r * LDH + c4 * 4) = v;
    }
    const uint2* W2 = (const uint2*)Wt;
    #pragma unroll
    for (int i = 0; i < 16; i++) {
        int f = tid + 256 * i;
        int r = f >> 5, c4 = f & 31;
        *(uint2*)(Ws + r * LDH + c4 * 4) = __ldg(W2 + f);
    }
    __syncthreads();

    wmma::fragment<wmma::accumulator, 16, 16, 16, float> acc[8];
    #pragma unroll
    for (int n = 0; n < 8; n++) wmma::fill_fragment(acc[n], 0.f);

    #pragma unroll
    for (int k = 0; k < 8; k++) {
        wmma::fragment<wmma::matrix_a, 16, 16, 16, __half, wmma::row_major> a;
        wmma::load_matrix_sync(a, Xs + (warp * 16) * LDH + k * 16, LDH);
        #pragma unroll
        for (int n = 0; n < 8; n++) {
            wmma::fragment<wmma::matrix_b, 16, 16, 16, __half, wmma::row_major> b;
            wmma::load_matrix_sync(b, Ws + (k * 16) * LDH + n * 16, LDH);
            wmma::mma_sync(acc[n], a, b, acc[n]);
        }
    }
    __syncthreads();

    #pragma unroll
    for (int n = 0; n < 8; n++)
        wmma::store_matrix_sync(Os + (warp * 16) * GTILE + n * 16, acc[n], GTILE,
                                wmma::mem_row_major);
    __syncthreads();

    float4 bv = __ldg((const float4*)bias + lane);
    #pragma unroll
    for (int i = 0; i < 16; i++) {
        int r = warp * 16 + i;
        int gr = row0 + r;
        if (gr >= N_NODES) break;
        float4 v = *(const float4*)(Os + r * GTILE + lane * 4);
        v.x += bv.x; v.y += bv.y; v.z += bv.z; v.w += bv.w;
        if (z == 0) {
            v.x = (v.x >= 0.f) ? v.x : 0.2f * v.x;
            v.y = (v.y >= 0.f) ? v.y : 0.2f * v.y;
            v.z = (v.z >= 0.f) ? v.z : 0.2f * v.z;
            v.w = (v.w >= 0.f) ? v.w : 0.2f * v.w;
        } else {
            int deg = __ldg(rp + gr + 1) - __ldg(rp + gr);
            if (deg == 0) {
                v = make_float4(0.f, 0.f, 0.f, 0.f);
            } else {
                float ss = v.x*v.x + v.y*v.y + v.z*v.z + v.w*v.w;
                #pragma unroll
                for (int o = 16; o; o >>= 1) ss += __shfl_xor_sync(0xffffffffu, ss, o);
                float ns = fmaxf(sqrtf(ss), EPSF);
                float sc = (z == 1) ? (tanhf(ns) / ns) : (1.f / ns);
                v.x *= sc; v.y *= sc; v.z *= sc; v.w *= sc;
            }
        }
        ((float4*)Y)[(size_t)gr * 32 + lane] = v;
    }
}

// ---------------- launch --------------------------------------------------------
extern "C" void kernel_launch(void* const* d_in, const int* in_sizes, int n_in,
                              void* d_out, int out_size) {
    const float* e_emb = (const float*)d_in[0];
    const float* b_emb = (const float*)d_in[1];
    const float* s_emb = (const float*)d_in[2];
    const float* W_e   = (const float*)d_in[3];
    const float* b_e   = (const float*)d_in[4];
    const float* W_b   = (const float*)d_in[5];
    const float* b_b   = (const float*)d_in[6];
    const float* W_s   = (const float*)d_in[7];
    const float* b_s   = (const float*)d_in[8];
    const int*   src   = (const int*)d_in[9];
    const int*   dst   = (const int*)d_in[10];

    float* out = (float*)d_out;

    __half *pack, *emean, *bmean, *smean, *Wth;
    int *counts, *rowptr, *cursor, *csr;
    cudaGetSymbolAddress((void**)&pack,   g_pack);
    cudaGetSymbolAddress((void**)&emean,  g_emean);
    cudaGetSymbolAddress((void**)&bmean,  g_bmean);
    cudaGetSymbolAddress((void**)&smean,  g_smean);
    cudaGetSymbolAddress((void**)&Wth,    g_Wth);
    cudaGetSymbolAddress((void**)&counts, g_counts);
    cudaGetSymbolAddress((void**)&rowptr, g_rowptr);
    cudaGetSymbolAddress((void**)&cursor, g_cursor);
    cudaGetSymbolAddress((void**)&csr,    g_csr);
    int* status = counts + N_NODES;

    const int GSMEM = 2 * GTILE * LDH * 2;   // 69632 B
    cudaFuncSetAttribute(gemm_wmma3, cudaFuncAttributeMaxDynamicSharedMemorySize, GSMEM);

    cudaMemsetAsync(counts, 0, (N_NODES + NBLK) * sizeof(int));
    hist_kernel<<<2048, 256>>>(dst, counts);
    scan_lookback<<<NBLK, 256>>>(counts, rowptr, cursor, status);
    scatter_pack_kernel<<<MERG_BLOCKS, 256>>>(src, dst, cursor, csr,
                                              e_emb, b_emb, s_emb, pack,
                                              W_e, W_b, W_s, Wth);
    agg_fused<<<(N_NODES * 32 + 255) / 256, 256>>>(pack, emean, bmean, smean, csr, rowptr);

    dim3 gg((N_NODES + GTILE - 1) / GTILE, 1, 3);   // 782 x 1 x 3
    gemm_wmma3<<<gg, 256, GSMEM>>>(emean, bmean, smean, Wth, b_e, b_b, b_s, out, rowptr);
}

// round 12
// speedup vs baseline: 1.1485x; 1.0153x over previous
#include <cuda_runtime.h>
#include <cuda_fp16.h>
#include <mma.h>
#include <math.h>

using namespace nvcuda;

#define N_NODES 100000
#define N_EDGES 1600000
#define DIM     128
#define EPSF    1e-12f
#define NBLK    ((N_NODES + 255) / 256)   // 391
#define GTILE   128
#define LDH     136

// block partition for the merged scatter+pack+transpose+zero launch
#define SCAT_BLOCKS 2048
#define PACK_BLOCKS 12500
#define TRAN_BLOCKS 48
#define ZERO_BLOCKS 112
#define MERG_BLOCKS (SCAT_BLOCKS + PACK_BLOCKS + TRAN_BLOCKS + ZERO_BLOCKS)

// ---------------- scratch (__device__ globals, zero-initialized) ---------------
__device__ __align__(16) __half g_pack[(size_t)N_NODES * 384];  // [e|b_tan|s_nrm] fp16
__device__ __align__(16) __half g_emean[(size_t)N_NODES * DIM];
__device__ __align__(16) __half g_bmean[(size_t)N_NODES * DIM];
__device__ __align__(16) __half g_smean[(size_t)N_NODES * DIM];
__device__ __align__(16) __half g_Wth [3 * DIM * DIM];          // W^T fp16
__device__ int   g_counts[N_NODES + NBLK];   // [counts | scan status]; re-zeroed per launch
__device__ int   g_rowptr[N_NODES + 1];
__device__ int   g_cursor[N_NODES];
__device__ int   g_csr   [N_EDGES];

// ---------------- helpers ------------------------------------------------------
__device__ __forceinline__ uint2 f4_to_h4(float4 v) {
    __half2 lo = __floats2half2_rn(v.x, v.y);
    __half2 hi = __floats2half2_rn(v.z, v.w);
    uint2 r;
    r.x = *(unsigned*)&lo;
    r.y = *(unsigned*)&hi;
    return r;
}

__device__ __forceinline__ void h4_acc(uint2 u, float4& a) {
    float2 lo = __half22float2(*(__half2*)&u.x);
    float2 hi = __half22float2(*(__half2*)&u.y);
    a.x += lo.x; a.y += lo.y; a.z += hi.x; a.w += hi.y;
}

// fp16 pairwise add (2x HADD2)
__device__ __forceinline__ uint2 h4_add(uint2 a, uint2 b) {
    __half2 ax = *(__half2*)&a.x, ay = *(__half2*)&a.y;
    __half2 bx = *(__half2*)&b.x, by = *(__half2*)&b.y;
    __half2 rx = __hadd2(ax, bx), ry = __hadd2(ay, by);
    uint2 r;
    r.x = *(unsigned*)&rx;
    r.y = *(unsigned*)&ry;
    return r;
}

// ---------------- hist (int4-vectorized edge reads) ------------------------------
__global__ void hist_kernel(const int4* __restrict__ dst4, int* __restrict__ counts) {
    int i = blockIdx.x * blockDim.x + threadIdx.x;
    int stride = gridDim.x * blockDim.x;
    const int n4 = N_EDGES / 4;   // 400000, exact
    for (int e = i; e < n4; e += stride) {
        int4 d = __ldg(dst4 + e);
        atomicAdd(counts + d.x, 1);
        atomicAdd(counts + d.y, 1);
        atomicAdd(counts + d.z, 1);
        atomicAdd(counts + d.w, 1);
    }
}

// ---------------- single-kernel decoupled-lookback scan -------------------------
__global__ void __launch_bounds__(256)
scan_lookback(const int* __restrict__ counts, int* __restrict__ rowptr,
              int* __restrict__ cursor, volatile int* status) {
    int b = blockIdx.x, t = threadIdx.x;
    int gid = b * 256 + t;
    int lane = t & 31, wid = t >> 5;
    int v = (gid < N_NODES) ? counts[gid] : 0;

    int x = v;
    #pragma unroll
    for (int o = 1; o < 32; o <<= 1) {
        int y = __shfl_up_sync(0xffffffffu, x, o);
        if (lane >= o) x += y;
    }
    __shared__ int wt[8];
    __shared__ int woff[8];
    __shared__ int s_prefix;
    __shared__ int s_total;
    if (lane == 31) wt[wid] = x;
    __syncthreads();

    if (t == 0) {
        int run = 0;
        #pragma unroll
        for (int i = 0; i < 8; i++) { woff[i] = run; run += wt[i]; }
        s_total = run;
        if (b == 0) {
            status[0] = (run << 2) | 2;
            s_prefix = 0;
        } else {
            status[b] = (run << 2) | 1;
            int running = 0;
            for (int p = b - 1; p >= 0;) {
                int s;
                do { s = status[p]; } while ((s & 3) == 0);
                running += (s >> 2);
                if ((s & 3) == 2) break;
                p--;
            }
            s_prefix = running;
            status[b] = ((running + run) << 2) | 2;
        }
    }
    __syncthreads();

    int ex = x - v + woff[wid] + s_prefix;
    if (gid < N_NODES) { rowptr[gid] = ex; cursor[gid] = ex; }
    if (t == 0 && b == NBLK - 1) rowptr[N_NODES] = s_prefix + s_total;
}

// ---------------- merged: scatter + pack + W transposes + counts re-zero --------
__global__ void __launch_bounds__(256)
scatter_pack_kernel(const int* __restrict__ src, const int* __restrict__ dst,
                    int* __restrict__ cursor, int* __restrict__ csr,
                    const float* __restrict__ e_emb, const float* __restrict__ b_emb,
                    const float* __restrict__ s_emb, __half* __restrict__ pack,
                    const float* __restrict__ W0, const float* __restrict__ W1,
                    const float* __restrict__ W2, __half* __restrict__ Wt,
                    int* __restrict__ counts) {
    int blk = blockIdx.x;

    if (blk < SCAT_BLOCKS) {
        int i = blk * 256 + threadIdx.x;
        int stride = SCAT_BLOCKS * 256;
        for (int e = i; e < N_EDGES; e += stride) {
            int d = __ldg(dst + e);
            int p = atomicAdd(cursor + d, 1);
            csr[p] = __ldg(src + e);
        }
    } else if (blk < SCAT_BLOCKS + PACK_BLOCKS) {
        int lane = threadIdx.x & 31;
        int node = ((blk - SCAT_BLOCKS) * 256 + (int)threadIdx.x) >> 5;
        if (node >= N_NODES) return;

        float4 e = __ldg((const float4*)e_emb + (size_t)node * 32 + lane);
        float4 b = __ldg((const float4*)b_emb + (size_t)node * 32 + lane);
        float4 s = __ldg((const float4*)s_emb + (size_t)node * 32 + lane);

        float nb = b.x*b.x + b.y*b.y + b.z*b.z + b.w*b.w;
        float ns = s.x*s.x + s.y*s.y + s.z*s.z + s.w*s.w;
        #pragma unroll
        for (int o = 16; o; o >>= 1) {
            nb += __shfl_xor_sync(0xffffffffu, nb, o);
            ns += __shfl_xor_sync(0xffffffffu, ns, o);
        }
        float bn_safe = fmaxf(sqrtf(nb), EPSF);
        float bn_cl   = fminf(bn_safe, 1.f - 1e-5f);
        float bsc = atanhf(bn_cl) / bn_safe;
        float ssc = 1.f / fmaxf(sqrtf(ns), EPSF);

        b.x *= bsc; b.y *= bsc; b.z *= bsc; b.w *= bsc;
        s.x *= ssc; s.y *= ssc; s.z *= ssc; s.w *= ssc;

        uint2* row = (uint2*)(pack + (size_t)node * 384);
        row[lane]      = f4_to_h4(e);
        row[32 + lane] = f4_to_h4(b);
        row[64 + lane] = f4_to_h4(s);
    } else if (blk < SCAT_BLOCKS + PACK_BLOCKS + TRAN_BLOCKS) {
        __shared__ float t[32][33];
        int tb = blk - SCAT_BLOCKS - PACK_BLOCKS;  // 0..47
        int z = tb >> 4;
        int tile = tb & 15;
        const float* W = (z == 0) ? W0 : (z == 1) ? W1 : W2;
        __half* D = Wt + z * DIM * DIM;
        int bx = (tile & 3) * 32, by = (tile >> 2) * 32;
        int x = threadIdx.x & 31, y = threadIdx.x >> 5;   // (32, 8)
        #pragma unroll
        for (int j = 0; j < 32; j += 8)
            t[y + j][x] = W[(by + y + j) * DIM + bx + x];
        __syncthreads();
        #pragma unroll
        for (int j = 0; j < 32; j += 8)
            D[(bx + y + j) * DIM + by + x] = __float2half(t[x][y + j]);
    } else {
        // re-zero counts + scan status for the NEXT graph replay
        // (scan_lookback has already consumed them this launch)
        int zb = blk - SCAT_BLOCKS - PACK_BLOCKS - TRAN_BLOCKS;   // 0..111
        int i = zb * 256 + threadIdx.x;
        int stride = ZERO_BLOCKS * 256;
        for (int k = i; k < N_NODES + NBLK; k += stride)
            counts[k] = 0;
    }
}

// ---------------- fused CSR mean-aggregate (fp16 out), warp per node -----------
// EXACT R8 config: x4 edge unroll, pairwise HADD2, 12 independent loads in flight.
__global__ void agg_fused(const __half* __restrict__ pack,
                          __half* __restrict__ em, __half* __restrict__ bm, __half* __restrict__ sm,
                          const int* __restrict__ csr, const int* __restrict__ rp) {
    int lane = threadIdx.x & 31;
    int node = (blockIdx.x * blockDim.x + threadIdx.x) >> 5;
    if (node >= N_NODES) return;

    int beg = __ldg(rp + node), end = __ldg(rp + node + 1);
    float4 ae = make_float4(0,0,0,0), ab = make_float4(0,0,0,0), as = make_float4(0,0,0,0);
    const uint2* p2 = (const uint2*)pack;

    for (int base = beg; base < end; base += 32) {
        int n = min(32, end - base);
        int sidx = (base + lane < end) ? __ldg(csr + base + lane) : 0;
        int j = 0;
        for (; j + 4 <= n; j += 4) {
            int s0 = __shfl_sync(0xffffffffu, sidx, j);
            int s1 = __shfl_sync(0xffffffffu, sidx, j + 1);
            int s2 = __shfl_sync(0xffffffffu, sidx, j + 2);
            int s3 = __shfl_sync(0xffffffffu, sidx, j + 3);
            const uint2* r0 = p2 + (size_t)s0 * 96;
            const uint2* r1 = p2 + (size_t)s1 * 96;
            const uint2* r2 = p2 + (size_t)s2 * 96;
            const uint2* r3 = p2 + (size_t)s3 * 96;
            uint2 e0 = __ldg(r0 + lane),      e1 = __ldg(r1 + lane);
            uint2 e2 = __ldg(r2 + lane),      e3 = __ldg(r3 + lane);
            uint2 b0 = __ldg(r0 + 32 + lane), b1 = __ldg(r1 + 32 + lane);
            uint2 b2 = __ldg(r2 + 32 + lane), b3 = __ldg(r3 + 32 + lane);
            uint2 c0 = __ldg(r0 + 64 + lane), c1 = __ldg(r1 + 64 + lane);
            uint2 c2 = __ldg(r2 + 64 + lane), c3 = __ldg(r3 + 64 + lane);
            h4_acc(h4_add(e0, e1), ae); h4_acc(h4_add(e2, e3), ae);
            h4_acc(h4_add(b0, b1), ab); h4_acc(h4_add(b2, b3), ab);
            h4_acc(h4_add(c0, c1), as); h4_acc(h4_add(c2, c3), as);
        }
        for (; j < n; j++) {
            int s0 = __shfl_sync(0xffffffffu, sidx, j);
            const uint2* r0 = p2 + (size_t)s0 * 96;
            h4_acc(__ldg(r0 + lane), ae);
            h4_acc(__ldg(r0 + 32 + lane), ab);
            h4_acc(__ldg(r0 + 64 + lane), as);
        }
    }

    int deg = end - beg;
    float inv = (deg > 0) ? (1.f / (float)deg) : 0.f;
    ae.x *= inv; ae.y *= inv; ae.z *= inv; ae.w *= inv;
    ab.x *= inv; ab.y *= inv; ab.z *= inv; ab.w *= inv;
    as.x *= inv; as.y *= inv; as.z *= inv; as.w *= inv;

    size_t o = (size_t)node * 32 + lane;
    ((uint2*)em)[o] = f4_to_h4(ae);
    ((uint2*)bm)[o] = f4_to_h4(ab);
    ((uint2*)sm)[o] = f4_to_h4(as);
}

// ---------------- WMMA GEMM (all 3 spaces in one launch, z = space) ------------
__global__ void __launch_bounds__(256)
gemm_wmma3(const __half* __restrict__ em, const __half* __restrict__ bm,
           const __half* __restrict__ sm, const __half* __restrict__ Wth,
           const float* __restrict__ b_e, const float* __restrict__ b_b,
           const float* __restrict__ b_s, float* __restrict__ out,
           const int* __restrict__ rp) {
    extern __shared__ char sh[];
    __half* Xs = (__half*)sh;                       // [128][136]
    __half* Ws = (__half*)(sh + GTILE * LDH * 2);   // [128][136]
    float*  Os = (float*)sh;                        // [128][128] aliases Xs/Ws

    int z = blockIdx.z;
    const __half* X    = (z == 0) ? em : (z == 1) ? bm : sm;
    const __half* Wt   = Wth + z * DIM * DIM;
    const float*  bias = (z == 0) ? b_e : (z == 1) ? b_b : b_s;
    float*        Y    = out + (size_t)z * N_NODES * DIM;

    int tid = threadIdx.x;
    int warp = tid >> 5, lane = tid & 31;
    int row0 = blockIdx.x * GTILE;

    const uint2* X2 = (const uint2*)X;
    #pragma unroll
    for (int i = 0; i < 16; i++) {
        int f = tid + 256 * i;
        int r = f >> 5, c4 = f & 31;
        int gr = row0 + r;
        uint2 v = make_uint2(0u, 0u);
        if (gr < N_NODES) v = __ldg(X2 + (size_t)gr * 32 + c4);
        *(uint2*)(Xs + r * LDH + c4 * 4) = v;
    }
    const uint2* W2 = (const uint2*)Wt;
    #pragma unroll
    for (int i = 0; i < 16; i++) {
        int f = tid + 256 * i;
        int r = f >> 5, c4 = f & 31;
        *(uint2*)(Ws + r * LDH + c4 * 4) = __ldg(W2 + f);
    }
    __syncthreads();

    wmma::fragment<wmma::accumulator, 16, 16, 16, float> acc[8];
    #pragma unroll
    for (int n = 0; n < 8; n++) wmma::fill_fragment(acc[n], 0.f);

    #pragma unroll
    for (int k = 0; k < 8; k++) {
        wmma::fragment<wmma::matrix_a, 16, 16, 16, __half, wmma::row_major> a;
        wmma::load_matrix_sync(a, Xs + (warp * 16) * LDH + k * 16, LDH);
        #pragma unroll
        for (int n = 0; n < 8; n++) {
            wmma::fragment<wmma::matrix_b, 16, 16, 16, __half, wmma::row_major> b;
            wmma::load_matrix_sync(b, Ws + (k * 16) * LDH + n * 16, LDH);
            wmma::mma_sync(acc[n], a, b, acc[n]);
        }
    }
    __syncthreads();

    #pragma unroll
    for (int n = 0; n < 8; n++)
        wmma::store_matrix_sync(Os + (warp * 16) * GTILE + n * 16, acc[n], GTILE,
                                wmma::mem_row_major);
    __syncthreads();

    float4 bv = __ldg((const float4*)bias + lane);
    #pragma unroll
    for (int i = 0; i < 16; i++) {
        int r = warp * 16 + i;
        int gr = row0 + r;
        if (gr >= N_NODES) break;
        float4 v = *(const float4*)(Os + r * GTILE + lane * 4);
        v.x += bv.x; v.y += bv.y; v.z += bv.z; v.w += bv.w;
        if (z == 0) {
            v.x = (v.x >= 0.f) ? v.x : 0.2f * v.x;
            v.y = (v.y >= 0.f) ? v.y : 0.2f * v.y;
            v.z = (v.z >= 0.f) ? v.z : 0.2f * v.z;
            v.w = (v.w >= 0.f) ? v.w : 0.2f * v.w;
        } else {
            int deg = __ldg(rp + gr + 1) - __ldg(rp + gr);
            if (deg == 0) {
                v = make_float4(0.f, 0.f, 0.f, 0.f);
            } else {
                float ss = v.x*v.x + v.y*v.y + v.z*v.z + v.w*v.w;
                #pragma unroll
                for (int o = 16; o; o >>= 1) ss += __shfl_xor_sync(0xffffffffu, ss, o);
                float ns = fmaxf(sqrtf(ss), EPSF);
                float sc = (z == 1) ? (tanhf(ns) / ns) : (1.f / ns);
                v.x *= sc; v.y *= sc; v.z *= sc; v.w *= sc;
            }
        }
        ((float4*)Y)[(size_t)gr * 32 + lane] = v;
    }
}

// ---------------- launch --------------------------------------------------------
extern "C" void kernel_launch(void* const* d_in, const int* in_sizes, int n_in,
                              void* d_out, int out_size) {
    const float* e_emb = (const float*)d_in[0];
    const float* b_emb = (const float*)d_in[1];
    const float* s_emb = (const float*)d_in[2];
    const float* W_e   = (const float*)d_in[3];
    const float* b_e   = (const float*)d_in[4];
    const float* W_b   = (const float*)d_in[5];
    const float* b_b   = (const float*)d_in[6];
    const float* W_s   = (const float*)d_in[7];
    const float* b_s   = (const float*)d_in[8];
    const int*   src   = (const int*)d_in[9];
    const int*   dst   = (const int*)d_in[10];

    float* out = (float*)d_out;

    __half *pack, *emean, *bmean, *smean, *Wth;
    int *counts, *rowptr, *cursor, *csr;
    cudaGetSymbolAddress((void**)&pack,   g_pack);
    cudaGetSymbolAddress((void**)&emean,  g_emean);
    cudaGetSymbolAddress((void**)&bmean,  g_bmean);
    cudaGetSymbolAddress((void**)&smean,  g_smean);
    cudaGetSymbolAddress((void**)&Wth,    g_Wth);
    cudaGetSymbolAddress((void**)&counts, g_counts);
    cudaGetSymbolAddress((void**)&rowptr, g_rowptr);
    cudaGetSymbolAddress((void**)&cursor, g_cursor);
    cudaGetSymbolAddress((void**)&csr,    g_csr);
    int* status = counts + N_NODES;

    const int GSMEM = 2 * GTILE * LDH * 2;   // 69632 B
    cudaFuncSetAttribute(gemm_wmma3, cudaFuncAttributeMaxDynamicSharedMemorySize, GSMEM);

    // counts/status are zero at entry: zero-initialized at module load, then
    // re-zeroed inside scatter_pack_kernel every launch (graph-replay invariant).
    hist_kernel<<<2048, 256>>>((const int4*)dst, counts);
    scan_lookback<<<NBLK, 256>>>(counts, rowptr, cursor, status);
    scatter_pack_kernel<<<MERG_BLOCKS, 256>>>(src, dst, cursor, csr,
                                              e_emb, b_emb, s_emb, pack,
                                              W_e, W_b, W_s, Wth, counts);
    agg_fused<<<(N_NODES * 32 + 255) / 256, 256>>>(pack, emean, bmean, smean, csr, rowptr);

    dim3 gg((N_NODES + GTILE - 1) / GTILE, 1, 3);   // 782 x 1 x 3
    gemm_wmma3<<<gg, 256, GSMEM>>>(emean, bmean, smean, Wth, b_e, b_b, b_s, out, rowptr);
}

// round 13
// speedup vs baseline: 1.1890x; 1.0353x over previous
#include <cuda_runtime.h>
#include <cuda_fp16.h>
#include <mma.h>
#include <math.h>

using namespace nvcuda;

#define N_NODES 100000
#define N_EDGES 1600000
#define DIM     128
#define EPSF    1e-12f
#define NBLK    ((N_NODES + 255) / 256)   // 391
#define GTILE   128
#define LDH     136

// block partition for the merged scatter+pack+transpose+zero launch
#define SCAT_BLOCKS 2048
#define PACK_BLOCKS 12500
#define TRAN_BLOCKS 48
#define ZERO_BLOCKS 112
#define MERG_BLOCKS (SCAT_BLOCKS + PACK_BLOCKS + TRAN_BLOCKS + ZERO_BLOCKS)

// ---------------- scratch (__device__ globals, zero-initialized) ---------------
__device__ __align__(16) __half g_pack[(size_t)N_NODES * 384];  // [e|b_tan|s_nrm] fp16
__device__ __align__(16) __half g_emean[(size_t)N_NODES * DIM];
__device__ __align__(16) __half g_bmean[(size_t)N_NODES * DIM];
__device__ __align__(16) __half g_smean[(size_t)N_NODES * DIM];
__device__ __align__(16) __half g_Wth [3 * DIM * DIM];          // W^T fp16
__device__ int   g_counts[N_NODES + NBLK];   // [counts | scan status]; re-zeroed per launch
__device__ int   g_rowptr[N_NODES + 1];
__device__ int   g_cursor[N_NODES];
__device__ int   g_csr   [N_EDGES];

// ---------------- helpers ------------------------------------------------------
__device__ __forceinline__ uint2 f4_to_h4(float4 v) {
    __half2 lo = __floats2half2_rn(v.x, v.y);
    __half2 hi = __floats2half2_rn(v.z, v.w);
    uint2 r;
    r.x = *(unsigned*)&lo;
    r.y = *(unsigned*)&hi;
    return r;
}

__device__ __forceinline__ void h4_acc(uint2 u, float4& a) {
    float2 lo = __half22float2(*(__half2*)&u.x);
    float2 hi = __half22float2(*(__half2*)&u.y);
    a.x += lo.x; a.y += lo.y; a.z += hi.x; a.w += hi.y;
}

// fp16 pairwise add (2x HADD2)
__device__ __forceinline__ uint2 h4_add(uint2 a, uint2 b) {
    __half2 ax = *(__half2*)&a.x, ay = *(__half2*)&a.y;
    __half2 bx = *(__half2*)&b.x, by = *(__half2*)&b.y;
    __half2 rx = __hadd2(ax, bx), ry = __hadd2(ay, by);
    uint2 r;
    r.x = *(unsigned*)&rx;
    r.y = *(unsigned*)&ry;
    return r;
}

// ---------------- hist (int4-vectorized edge reads) ------------------------------
__global__ void hist_kernel(const int4* __restrict__ dst4, int* __restrict__ counts) {
    int i = blockIdx.x * blockDim.x + threadIdx.x;
    int stride = gridDim.x * blockDim.x;
    const int n4 = N_EDGES / 4;   // 400000, exact
    for (int e = i; e < n4; e += stride) {
        int4 d = __ldg(dst4 + e);
        atomicAdd(counts + d.x, 1);
        atomicAdd(counts + d.y, 1);
        atomicAdd(counts + d.z, 1);
        atomicAdd(counts + d.w, 1);
    }
}

// ---------------- single-kernel decoupled-lookback scan -------------------------
__global__ void __launch_bounds__(256)
scan_lookback(const int* __restrict__ counts, int* __restrict__ rowptr,
              int* __restrict__ cursor, volatile int* status) {
    int b = blockIdx.x, t = threadIdx.x;
    int gid = b * 256 + t;
    int lane = t & 31, wid = t >> 5;
    int v = (gid < N_NODES) ? counts[gid] : 0;

    int x = v;
    #pragma unroll
    for (int o = 1; o < 32; o <<= 1) {
        int y = __shfl_up_sync(0xffffffffu, x, o);
        if (lane >= o) x += y;
    }
    __shared__ int wt[8];
    __shared__ int woff[8];
    __shared__ int s_prefix;
    __shared__ int s_total;
    if (lane == 31) wt[wid] = x;
    __syncthreads();

    if (t == 0) {
        int run = 0;
        #pragma unroll
        for (int i = 0; i < 8; i++) { woff[i] = run; run += wt[i]; }
        s_total = run;
        if (b == 0) {
            status[0] = (run << 2) | 2;
            s_prefix = 0;
        } else {
            status[b] = (run << 2) | 1;
            int running = 0;
            for (int p = b - 1; p >= 0;) {
                int s;
                do { s = status[p]; } while ((s & 3) == 0);
                running += (s >> 2);
                if ((s & 3) == 2) break;
                p--;
            }
            s_prefix = running;
            status[b] = ((running + run) << 2) | 2;
        }
    }
    __syncthreads();

    int ex = x - v + woff[wid] + s_prefix;
    if (gid < N_NODES) { rowptr[gid] = ex; cursor[gid] = ex; }
    if (t == 0 && b == NBLK - 1) rowptr[N_NODES] = s_prefix + s_total;
}

// ---------------- merged: scatter + pack + W transposes + counts re-zero --------
__global__ void __launch_bounds__(256)
scatter_pack_kernel(const int4* __restrict__ src4, const int4* __restrict__ dst4,
                    int* __restrict__ cursor, int* __restrict__ csr,
                    const float* __restrict__ e_emb, const float* __restrict__ b_emb,
                    const float* __restrict__ s_emb, __half* __restrict__ pack,
                    const float* __restrict__ W0, const float* __restrict__ W1,
                    const float* __restrict__ W2, __half* __restrict__ Wt,
                    int* __restrict__ counts) {
    int blk = blockIdx.x;

    if (blk < SCAT_BLOCKS) {
        // ---- CSR scatter, 4 edges per iteration ----
        int i = blk * 256 + threadIdx.x;
        int stride = SCAT_BLOCKS * 256;
        const int n4 = N_EDGES / 4;   // exact
        for (int e = i; e < n4; e += stride) {
            int4 s = __ldg(src4 + e);
            int4 d = __ldg(dst4 + e);
            csr[atomicAdd(cursor + d.x, 1)] = s.x;
            csr[atomicAdd(cursor + d.y, 1)] = s.y;
            csr[atomicAdd(cursor + d.z, 1)] = s.z;
            csr[atomicAdd(cursor + d.w, 1)] = s.w;
        }
    } else if (blk < SCAT_BLOCKS + PACK_BLOCKS) {
        int lane = threadIdx.x & 31;
        int node = ((blk - SCAT_BLOCKS) * 256 + (int)threadIdx.x) >> 5;
        if (node >= N_NODES) return;

        float4 e = __ldg((const float4*)e_emb + (size_t)node * 32 + lane);
        float4 b = __ldg((const float4*)b_emb + (size_t)node * 32 + lane);
        float4 s = __ldg((const float4*)s_emb + (size_t)node * 32 + lane);

        float nb = b.x*b.x + b.y*b.y + b.z*b.z + b.w*b.w;
        float ns = s.x*s.x + s.y*s.y + s.z*s.z + s.w*s.w;
        #pragma unroll
        for (int o = 16; o; o >>= 1) {
            nb += __shfl_xor_sync(0xffffffffu, nb, o);
            ns += __shfl_xor_sync(0xffffffffu, ns, o);
        }
        float bn_safe = fmaxf(sqrtf(nb), EPSF);
        float bn_cl   = fminf(bn_safe, 1.f - 1e-5f);
        float bsc = atanhf(bn_cl) / bn_safe;
        float ssc = 1.f / fmaxf(sqrtf(ns), EPSF);

        b.x *= bsc; b.y *= bsc; b.z *= bsc; b.w *= bsc;
        s.x *= ssc; s.y *= ssc; s.z *= ssc; s.w *= ssc;

        uint2* row = (uint2*)(pack + (size_t)node * 384);
        row[lane]      = f4_to_h4(e);
        row[32 + lane] = f4_to_h4(b);
        row[64 + lane] = f4_to_h4(s);
    } else if (blk < SCAT_BLOCKS + PACK_BLOCKS + TRAN_BLOCKS) {
        __shared__ float t[32][33];
        int tb = blk - SCAT_BLOCKS - PACK_BLOCKS;  // 0..47
        int z = tb >> 4;
        int tile = tb & 15;
        const float* W = (z == 0) ? W0 : (z == 1) ? W1 : W2;
        __half* D = Wt + z * DIM * DIM;
        int bx = (tile & 3) * 32, by = (tile >> 2) * 32;
        int x = threadIdx.x & 31, y = threadIdx.x >> 5;   // (32, 8)
        #pragma unroll
        for (int j = 0; j < 32; j += 8)
            t[y + j][x] = W[(by + y + j) * DIM + bx + x];
        __syncthreads();
        #pragma unroll
        for (int j = 0; j < 32; j += 8)
            D[(bx + y + j) * DIM + by + x] = __float2half(t[x][y + j]);
    } else {
        // re-zero counts + scan status for the NEXT graph replay
        int zb = blk - SCAT_BLOCKS - PACK_BLOCKS - TRAN_BLOCKS;   // 0..111
        int i = zb * 256 + threadIdx.x;
        int stride = ZERO_BLOCKS * 256;
        for (int k = i; k < N_NODES + NBLK; k += stride)
            counts[k] = 0;
    }
}

// ---------------- fused CSR mean-aggregate (fp16 out), warp per node -----------
// EXACT R8 inner loop; blockDim 64 (2 warps) for fine-grained block retirement
// so degree imbalance doesn't strand finished warps.
__global__ void agg_fused(const __half* __restrict__ pack,
                          __half* __restrict__ em, __half* __restrict__ bm, __half* __restrict__ sm,
                          const int* __restrict__ csr, const int* __restrict__ rp) {
    int lane = threadIdx.x & 31;
    int node = (blockIdx.x * blockDim.x + threadIdx.x) >> 5;
    if (node >= N_NODES) return;

    int beg = __ldg(rp + node), end = __ldg(rp + node + 1);
    float4 ae = make_float4(0,0,0,0), ab = make_float4(0,0,0,0), as = make_float4(0,0,0,0);
    const uint2* p2 = (const uint2*)pack;

    for (int base = beg; base < end; base += 32) {
        int n = min(32, end - base);
        int sidx = (base + lane < end) ? __ldg(csr + base + lane) : 0;
        int j = 0;
        for (; j + 4 <= n; j += 4) {
            int s0 = __shfl_sync(0xffffffffu, sidx, j);
            int s1 = __shfl_sync(0xffffffffu, sidx, j + 1);
            int s2 = __shfl_sync(0xffffffffu, sidx, j + 2);
            int s3 = __shfl_sync(0xffffffffu, sidx, j + 3);
            const uint2* r0 = p2 + (size_t)s0 * 96;
            const uint2* r1 = p2 + (size_t)s1 * 96;
            const uint2* r2 = p2 + (size_t)s2 * 96;
            const uint2* r3 = p2 + (size_t)s3 * 96;
            uint2 e0 = __ldg(r0 + lane),      e1 = __ldg(r1 + lane);
            uint2 e2 = __ldg(r2 + lane),      e3 = __ldg(r3 + lane);
            uint2 b0 = __ldg(r0 + 32 + lane), b1 = __ldg(r1 + 32 + lane);
            uint2 b2 = __ldg(r2 + 32 + lane), b3 = __ldg(r3 + 32 + lane);
            uint2 c0 = __ldg(r0 + 64 + lane), c1 = __ldg(r1 + 64 + lane);
            uint2 c2 = __ldg(r2 + 64 + lane), c3 = __ldg(r3 + 64 + lane);
            h4_acc(h4_add(e0, e1), ae); h4_acc(h4_add(e2, e3), ae);
            h4_acc(h4_add(b0, b1), ab); h4_acc(h4_add(b2, b3), ab);
            h4_acc(h4_add(c0, c1), as); h4_acc(h4_add(c2, c3), as);
        }
        for (; j < n; j++) {
            int s0 = __shfl_sync(0xffffffffu, sidx, j);
            const uint2* r0 = p2 + (size_t)s0 * 96;
            h4_acc(__ldg(r0 + lane), ae);
            h4_acc(__ldg(r0 + 32 + lane), ab);
            h4_acc(__ldg(r0 + 64 + lane), as);
        }
    }

    int deg = end - beg;
    float inv = (deg > 0) ? (1.f / (float)deg) : 0.f;
    ae.x *= inv; ae.y *= inv; ae.z *= inv; ae.w *= inv;
    ab.x *= inv; ab.y *= inv; ab.z *= inv; ab.w *= inv;
    as.x *= inv; as.y *= inv; as.z *= inv; as.w *= inv;

    size_t o = (size_t)node * 32 + lane;
    ((uint2*)em)[o] = f4_to_h4(ae);
    ((uint2*)bm)[o] = f4_to_h4(ab);
    ((uint2*)sm)[o] = f4_to_h4(as);
}

// ---------------- WMMA GEMM (all 3 spaces in one launch, z = space) ------------
__global__ void __launch_bounds__(256)
gemm_wmma3(const __half* __restrict__ em, const __half* __restrict__ bm,
           const __half* __restrict__ sm, const __half* __restrict__ Wth,
           const float* __restrict__ b_e, const float* __restrict__ b_b,
           const float* __restrict__ b_s, float* __restrict__ out,
           const int* __restrict__ rp) {
    extern __shared__ char sh[];
    __half* Xs = (__half*)sh;                       // [128][136]
    __half* Ws = (__half*)(sh + GTILE * LDH * 2);   // [128][136]
    float*  Os = (float*)sh;                        // [128][128] aliases Xs/Ws

    int z = blockIdx.z;
    const __half* X    = (z == 0) ? em : (z == 1) ? bm : sm;
    const __half* Wt   = Wth + z * DIM * DIM;
    const float*  bias = (z == 0) ? b_e : (z == 1) ? b_b : b_s;
    float*        Y    = out + (size_t)z * N_NODES * DIM;

    int tid = threadIdx.x;
    int warp = tid >> 5, lane = tid & 31;
    int row0 = blockIdx.x * GTILE;

    const uint2* X2 = (const uint2*)X;
    #pragma unroll
    for (int i = 0; i < 16; i++) {
        int f = tid + 256 * i;
        int r = f >> 5, c4 = f & 31;
        int gr = row0 + r;
        uint2 v = make_uint2(0u, 0u);
        if (gr < N_NODES) v = __ldg(X2 + (size_t)gr * 32 + c4);
        *(uint2*)(Xs + r * LDH + c4 * 4) = v;
    }
    const uint2* W2 = (const uint2*)Wt;
    #pragma unroll
    for (int i = 0; i < 16; i++) {
        int f = tid + 256 * i;
        int r = f >> 5, c4 = f & 31;
        *(uint2*)(Ws + r * LDH + c4 * 4) = __ldg(W2 + f);
    }
    __syncthreads();

    wmma::fragment<wmma::accumulator, 16, 16, 16, float> acc[8];
    #pragma unroll
    for (int n = 0; n < 8; n++) wmma::fill_fragment(acc[n], 0.f);

    #pragma unroll
    for (int k = 0; k < 8; k++) {
        wmma::fragment<wmma::matrix_a, 16, 16, 16, __half, wmma::row_major> a;
        wmma::load_matrix_sync(a, Xs + (warp * 16) * LDH + k * 16, LDH);
        #pragma unroll
        for (int n = 0; n < 8; n++) {
            wmma::fragment<wmma::matrix_b, 16, 16, 16, __half, wmma::row_major> b;
            wmma::load_matrix_sync(b, Ws + (k * 16) * LDH + n * 16, LDH);
            wmma::mma_sync(acc[n], a, b, acc[n]);
        }
    }
    __syncthreads();

    #pragma unroll
    for (int n = 0; n < 8; n++)
        wmma::store_matrix_sync(Os + (warp * 16) * GTILE + n * 16, acc[n], GTILE,
                                wmma::mem_row_major);
    __syncthreads();

    float4 bv = __ldg((const float4*)bias + lane);
    #pragma unroll
    for (int i = 0; i < 16; i++) {
        int r = warp * 16 + i;
        int gr = row0 + r;
        if (gr >= N_NODES) break;
        float4 v = *(const float4*)(Os + r * GTILE + lane * 4);
        v.x += bv.x; v.y += bv.y; v.z += bv.z; v.w += bv.w;
        if (z == 0) {
            v.x = (v.x >= 0.f) ? v.x : 0.2f * v.x;
            v.y = (v.y >= 0.f) ? v.y : 0.2f * v.y;
            v.z = (v.z >= 0.f) ? v.z : 0.2f * v.z;
            v.w = (v.w >= 0.f) ? v.w : 0.2f * v.w;
        } else {
            int deg = __ldg(rp + gr + 1) - __ldg(rp + gr);
            if (deg == 0) {
                v = make_float4(0.f, 0.f, 0.f, 0.f);
            } else {
                float ss = v.x*v.x + v.y*v.y + v.z*v.z + v.w*v.w;
                #pragma unroll
                for (int o = 16; o; o >>= 1) ss += __shfl_xor_sync(0xffffffffu, ss, o);
                float ns = fmaxf(sqrtf(ss), EPSF);
                float sc = (z == 1) ? (tanhf(ns) / ns) : (1.f / ns);
                v.x *= sc; v.y *= sc; v.z *= sc; v.w *= sc;
            }
        }
        ((float4*)Y)[(size_t)gr * 32 + lane] = v;
    }
}

// ---------------- launch --------------------------------------------------------
extern "C" void kernel_launch(void* const* d_in, const int* in_sizes, int n_in,
                              void* d_out, int out_size) {
    const float* e_emb = (const float*)d_in[0];
    const float* b_emb = (const float*)d_in[1];
    const float* s_emb = (const float*)d_in[2];
    const float* W_e   = (const float*)d_in[3];
    const float* b_e   = (const float*)d_in[4];
    const float* W_b   = (const float*)d_in[5];
    const float* b_b   = (const float*)d_in[6];
    const float* W_s   = (const float*)d_in[7];
    const float* b_s   = (const float*)d_in[8];
    const int*   src   = (const int*)d_in[9];
    const int*   dst   = (const int*)d_in[10];

    float* out = (float*)d_out;

    __half *pack, *emean, *bmean, *smean, *Wth;
    int *counts, *rowptr, *cursor, *csr;
    cudaGetSymbolAddress((void**)&pack,   g_pack);
    cudaGetSymbolAddress((void**)&emean,  g_emean);
    cudaGetSymbolAddress((void**)&bmean,  g_bmean);
    cudaGetSymbolAddress((void**)&smean,  g_smean);
    cudaGetSymbolAddress((void**)&Wth,    g_Wth);
    cudaGetSymbolAddress((void**)&counts, g_counts);
    cudaGetSymbolAddress((void**)&rowptr, g_rowptr);
    cudaGetSymbolAddress((void**)&cursor, g_cursor);
    cudaGetSymbolAddress((void**)&csr,    g_csr);
    int* status = counts + N_NODES;

    const int GSMEM = 2 * GTILE * LDH * 2;   // 69632 B
    cudaFuncSetAttribute(gemm_wmma3, cudaFuncAttributeMaxDynamicSharedMemorySize, GSMEM);

    // counts/status are zero at entry: zero-initialized at module load, then
    // re-zeroed inside scatter_pack_kernel every launch (graph-replay invariant).
    hist_kernel<<<2048, 256>>>((const int4*)dst, counts);
    scan_lookback<<<NBLK, 256>>>(counts, rowptr, cursor, status);
    scatter_pack_kernel<<<MERG_BLOCKS, 256>>>((const int4*)src, (const int4*)dst,
                                              cursor, csr,
                                              e_emb, b_emb, s_emb, pack,
                                              W_e, W_b, W_s, Wth, counts);

    // agg: 2-warp blocks for fine retirement granularity under degree imbalance
    agg_fused<<<(N_NODES * 32 + 63) / 64, 64>>>(pack, emean, bmean, smean, csr, rowptr);

    dim3 gg((N_NODES + GTILE - 1) / GTILE, 1, 3);   // 782 x 1 x 3
    gemm_wmma3<<<gg, 256, GSMEM>>>(emean, bmean, smean, Wth, b_e, b_b, b_s, out, rowptr);
}

// round 14
// speedup vs baseline: 1.2043x; 1.0129x over previous
#include <cuda_runtime.h>
#include <cuda_fp16.h>
#include <mma.h>
#include <math.h>

using namespace nvcuda;

#define N_NODES 100000
#define N_EDGES 1600000
#define DIM     128
#define EPSF    1e-12f
#define NBLK    ((N_NODES + 255) / 256)   // 391
#define GTILE   128
#define LDH     136

// block partition for the merged scatter+pack+transpose+zero launch
#define SCAT_BLOCKS 2048
#define PACK_BLOCKS 12500
#define TRAN_BLOCKS 48
#define ZERO_BLOCKS 112
#define MERG_BLOCKS (SCAT_BLOCKS + PACK_BLOCKS + TRAN_BLOCKS + ZERO_BLOCKS)

// ---------------- scratch (__device__ globals, zero-initialized) ---------------
__device__ __align__(16) __half g_pack[(size_t)N_NODES * 384];  // [e|b_tan|s_nrm] fp16
__device__ __align__(16) __half g_emean[(size_t)N_NODES * DIM];
__device__ __align__(16) __half g_bmean[(size_t)N_NODES * DIM];
__device__ __align__(16) __half g_smean[(size_t)N_NODES * DIM];
__device__ __align__(16) __half g_Wth [3 * DIM * DIM];          // W^T fp16
__device__ int   g_counts[N_NODES + NBLK];   // [counts | scan status]; re-zeroed per launch
__device__ int   g_rowptr[N_NODES + 1];
__device__ int   g_cursor[N_NODES];
__device__ int   g_csr   [N_EDGES];

// ---------------- helpers ------------------------------------------------------
__device__ __forceinline__ uint2 f4_to_h4(float4 v) {
    __half2 lo = __floats2half2_rn(v.x, v.y);
    __half2 hi = __floats2half2_rn(v.z, v.w);
    uint2 r;
    r.x = *(unsigned*)&lo;
    r.y = *(unsigned*)&hi;
    return r;
}

__device__ __forceinline__ void h4_acc(uint2 u, float4& a) {
    float2 lo = __half22float2(*(__half2*)&u.x);
    float2 hi = __half22float2(*(__half2*)&u.y);
    a.x += lo.x; a.y += lo.y; a.z += hi.x; a.w += hi.y;
}

// fp16 pairwise add (2x HADD2)
__device__ __forceinline__ uint2 h4_add(uint2 a, uint2 b) {
    __half2 ax = *(__half2*)&a.x, ay = *(__half2*)&a.y;
    __half2 bx = *(__half2*)&b.x, by = *(__half2*)&b.y;
    __half2 rx = __hadd2(ax, bx), ry = __hadd2(ay, by);
    uint2 r;
    r.x = *(unsigned*)&rx;
    r.y = *(unsigned*)&ry;
    return r;
}

// ---------------- hist (int4-vectorized, streaming reads) -----------------------
__global__ void hist_kernel(const int4* __restrict__ dst4, int* __restrict__ counts) {
    int i = blockIdx.x * blockDim.x + threadIdx.x;
    int stride = gridDim.x * blockDim.x;
    const int n4 = N_EDGES / 4;   // 400000, exact
    for (int e = i; e < n4; e += stride) {
        int4 d = __ldcs(dst4 + e);
        atomicAdd(counts + d.x, 1);
        atomicAdd(counts + d.y, 1);
        atomicAdd(counts + d.z, 1);
        atomicAdd(counts + d.w, 1);
    }
}

// ---------------- single-kernel decoupled-lookback scan -------------------------
__global__ void __launch_bounds__(256)
scan_lookback(const int* __restrict__ counts, int* __restrict__ rowptr,
              int* __restrict__ cursor, volatile int* status) {
    int b = blockIdx.x, t = threadIdx.x;
    int gid = b * 256 + t;
    int lane = t & 31, wid = t >> 5;
    int v = (gid < N_NODES) ? counts[gid] : 0;

    int x = v;
    #pragma unroll
    for (int o = 1; o < 32; o <<= 1) {
        int y = __shfl_up_sync(0xffffffffu, x, o);
        if (lane >= o) x += y;
    }
    __shared__ int wt[8];
    __shared__ int woff[8];
    __shared__ int s_prefix;
    __shared__ int s_total;
    if (lane == 31) wt[wid] = x;
    __syncthreads();

    if (t == 0) {
        int run = 0;
        #pragma unroll
        for (int i = 0; i < 8; i++) { woff[i] = run; run += wt[i]; }
        s_total = run;
        if (b == 0) {
            status[0] = (run << 2) | 2;
            s_prefix = 0;
        } else {
            status[b] = (run << 2) | 1;
            int running = 0;
            for (int p = b - 1; p >= 0;) {
                int s;
                do { s = status[p]; } while ((s & 3) == 0);
                running += (s >> 2);
                if ((s & 3) == 2) break;
                p--;
            }
            s_prefix = running;
            status[b] = ((running + run) << 2) | 2;
        }
    }
    __syncthreads();

    int ex = x - v + woff[wid] + s_prefix;
    if (gid < N_NODES) { rowptr[gid] = ex; cursor[gid] = ex; }
    if (t == 0 && b == NBLK - 1) rowptr[N_NODES] = s_prefix + s_total;
}

// ---------------- merged: scatter + pack + W transposes + counts re-zero --------
__global__ void __launch_bounds__(256)
scatter_pack_kernel(const int4* __restrict__ src4, const int4* __restrict__ dst4,
                    int* __restrict__ cursor, int* __restrict__ csr,
                    const float* __restrict__ e_emb, const float* __restrict__ b_emb,
                    const float* __restrict__ s_emb, __half* __restrict__ pack,
                    const float* __restrict__ W0, const float* __restrict__ W1,
                    const float* __restrict__ W2, __half* __restrict__ Wt,
                    int* __restrict__ counts) {
    int blk = blockIdx.x;

    if (blk < SCAT_BLOCKS) {
        // ---- CSR scatter, 4 edges per iteration, streaming edge reads ----
        int i = blk * 256 + threadIdx.x;
        int stride = SCAT_BLOCKS * 256;
        const int n4 = N_EDGES / 4;   // exact
        for (int e = i; e < n4; e += stride) {
            int4 s = __ldcs(src4 + e);
            int4 d = __ldcs(dst4 + e);
            csr[atomicAdd(cursor + d.x, 1)] = s.x;
            csr[atomicAdd(cursor + d.y, 1)] = s.y;
            csr[atomicAdd(cursor + d.z, 1)] = s.z;
            csr[atomicAdd(cursor + d.w, 1)] = s.w;
        }
    } else if (blk < SCAT_BLOCKS + PACK_BLOCKS) {
        int lane = threadIdx.x & 31;
        int node = ((blk - SCAT_BLOCKS) * 256 + (int)threadIdx.x) >> 5;
        if (node >= N_NODES) return;

        float4 e = __ldcs((const float4*)e_emb + (size_t)node * 32 + lane);
        float4 b = __ldcs((const float4*)b_emb + (size_t)node * 32 + lane);
        float4 s = __ldcs((const float4*)s_emb + (size_t)node * 32 + lane);

        float nb = b.x*b.x + b.y*b.y + b.z*b.z + b.w*b.w;
        float ns = s.x*s.x + s.y*s.y + s.z*s.z + s.w*s.w;
        #pragma unroll
        for (int o = 16; o; o >>= 1) {
            nb += __shfl_xor_sync(0xffffffffu, nb, o);
            ns += __shfl_xor_sync(0xffffffffu, ns, o);
        }
        float bn_safe = fmaxf(sqrtf(nb), EPSF);
        float bn_cl   = fminf(bn_safe, 1.f - 1e-5f);
        float bsc = atanhf(bn_cl) / bn_safe;
        float ssc = 1.f / fmaxf(sqrtf(ns), EPSF);

        b.x *= bsc; b.y *= bsc; b.z *= bsc; b.w *= bsc;
        s.x *= ssc; s.y *= ssc; s.z *= ssc; s.w *= ssc;

        uint2* row = (uint2*)(pack + (size_t)node * 384);
        row[lane]      = f4_to_h4(e);
        row[32 + lane] = f4_to_h4(b);
        row[64 + lane] = f4_to_h4(s);
    } else if (blk < SCAT_BLOCKS + PACK_BLOCKS + TRAN_BLOCKS) {
        __shared__ float t[32][33];
        int tb = blk - SCAT_BLOCKS - PACK_BLOCKS;  // 0..47
        int z = tb >> 4;
        int tile = tb & 15;
        const float* W = (z == 0) ? W0 : (z == 1) ? W1 : W2;
        __half* D = Wt + z * DIM * DIM;
        int bx = (tile & 3) * 32, by = (tile >> 2) * 32;
        int x = threadIdx.x & 31, y = threadIdx.x >> 5;   // (32, 8)
        #pragma unroll
        for (int j = 0; j < 32; j += 8)
            t[y + j][x] = W[(by + y + j) * DIM + bx + x];
        __syncthreads();
        #pragma unroll
        for (int j = 0; j < 32; j += 8)
            D[(bx + y + j) * DIM + by + x] = __float2half(t[x][y + j]);
    } else {
        // re-zero counts + scan status for the NEXT graph replay
        int zb = blk - SCAT_BLOCKS - PACK_BLOCKS - TRAN_BLOCKS;   // 0..111
        int i = zb * 256 + threadIdx.x;
        int stride = ZERO_BLOCKS * 256;
        for (int k = i; k < N_NODES + NBLK; k += stride)
            counts[k] = 0;
    }
}

// ---------------- fused CSR mean-aggregate (fp16 out), warp per node -----------
// EXACT R13 inner loop; mean writes use streaming hint (__stcs) so they do not
// evict the L2-resident pack working set that the gather depends on.
__global__ void agg_fused(const __half* __restrict__ pack,
                          __half* __restrict__ em, __half* __restrict__ bm, __half* __restrict__ sm,
                          const int* __restrict__ csr, const int* __restrict__ rp) {
    int lane = threadIdx.x & 31;
    int node = (blockIdx.x * blockDim.x + threadIdx.x) >> 5;
    if (node >= N_NODES) return;

    int beg = __ldg(rp + node), end = __ldg(rp + node + 1);
    float4 ae = make_float4(0,0,0,0), ab = make_float4(0,0,0,0), as = make_float4(0,0,0,0);
    const uint2* p2 = (const uint2*)pack;

    for (int base = beg; base < end; base += 32) {
        int n = min(32, end - base);
        int sidx = (base + lane < end) ? __ldg(csr + base + lane) : 0;
        int j = 0;
        for (; j + 4 <= n; j += 4) {
            int s0 = __shfl_sync(0xffffffffu, sidx, j);
            int s1 = __shfl_sync(0xffffffffu, sidx, j + 1);
            int s2 = __shfl_sync(0xffffffffu, sidx, j + 2);
            int s3 = __shfl_sync(0xffffffffu, sidx, j + 3);
            const uint2* r0 = p2 + (size_t)s0 * 96;
            const uint2* r1 = p2 + (size_t)s1 * 96;
            const uint2* r2 = p2 + (size_t)s2 * 96;
            const uint2* r3 = p2 + (size_t)s3 * 96;
            uint2 e0 = __ldg(r0 + lane),      e1 = __ldg(r1 + lane);
            uint2 e2 = __ldg(r2 + lane),      e3 = __ldg(r3 + lane);
            uint2 b0 = __ldg(r0 + 32 + lane), b1 = __ldg(r1 + 32 + lane);
            uint2 b2 = __ldg(r2 + 32 + lane), b3 = __ldg(r3 + 32 + lane);
            uint2 c0 = __ldg(r0 + 64 + lane), c1 = __ldg(r1 + 64 + lane);
            uint2 c2 = __ldg(r2 + 64 + lane), c3 = __ldg(r3 + 64 + lane);
            h4_acc(h4_add(e0, e1), ae); h4_acc(h4_add(e2, e3), ae);
            h4_acc(h4_add(b0, b1), ab); h4_acc(h4_add(b2, b3), ab);
            h4_acc(h4_add(c0, c1), as); h4_acc(h4_add(c2, c3), as);
        }
        for (; j < n; j++) {
            int s0 = __shfl_sync(0xffffffffu, sidx, j);
            const uint2* r0 = p2 + (size_t)s0 * 96;
            h4_acc(__ldg(r0 + lane), ae);
            h4_acc(__ldg(r0 + 32 + lane), ab);
            h4_acc(__ldg(r0 + 64 + lane), as);
        }
    }

    int deg = end - beg;
    float inv = (deg > 0) ? (1.f / (float)deg) : 0.f;
    ae.x *= inv; ae.y *= inv; ae.z *= inv; ae.w *= inv;
    ab.x *= inv; ab.y *= inv; ab.z *= inv; ab.w *= inv;
    as.x *= inv; as.y *= inv; as.z *= inv; as.w *= inv;

    size_t o = (size_t)node * 32 + lane;
    __stcs((uint2*)em + o, f4_to_h4(ae));
    __stcs((uint2*)bm + o, f4_to_h4(ab));
    __stcs((uint2*)sm + o, f4_to_h4(as));
}

// ---------------- WMMA GEMM (all 3 spaces in one launch, z = space) ------------
__global__ void __launch_bounds__(256)
gemm_wmma3(const __half* __restrict__ em, const __half* __restrict__ bm,
           const __half* __restrict__ sm, const __half* __restrict__ Wth,
           const float* __restrict__ b_e, const float* __restrict__ b_b,
           const float* __restrict__ b_s, float* __restrict__ out,
           const int* __restrict__ rp) {
    extern __shared__ char sh[];
    __half* Xs = (__half*)sh;                       // [128][136]
    __half* Ws = (__half*)(sh + GTILE * LDH * 2);   // [128][136]
    float*  Os = (float*)sh;                        // [128][128] aliases Xs/Ws

    int z = blockIdx.z;
    const __half* X    = (z == 0) ? em : (z == 1) ? bm : sm;
    const __half* Wt   = Wth + z * DIM * DIM;
    const float*  bias = (z == 0) ? b_e : (z == 1) ? b_b : b_s;
    float*        Y    = out + (size_t)z * N_NODES * DIM;

    int tid = threadIdx.x;
    int warp = tid >> 5, lane = tid & 31;
    int row0 = blockIdx.x * GTILE;

    const uint2* X2 = (const uint2*)X;
    #pragma unroll
    for (int i = 0; i < 16; i++) {
        int f = tid + 256 * i;
        int r = f >> 5, c4 = f & 31;
        int gr = row0 + r;
        uint2 v = make_uint2(0u, 0u);
        if (gr < N_NODES) v = __ldcs(X2 + (size_t)gr * 32 + c4);   // read-once stream
        *(uint2*)(Xs + r * LDH + c4 * 4) = v;
    }
    const uint2* W2 = (const uint2*)Wt;
    #pragma unroll
    for (int i = 0; i < 16; i++) {
        int f = tid + 256 * i;
        int r = f >> 5, c4 = f & 31;
        *(uint2*)(Ws + r * LDH + c4 * 4) = __ldg(W2 + f);          // reused: keep cached
    }
    __syncthreads();

    wmma::fragment<wmma::accumulator, 16, 16, 16, float> acc[8];
    #pragma unroll
    for (int n = 0; n < 8; n++) wmma::fill_fragment(acc[n], 0.f);

    #pragma unroll
    for (int k = 0; k < 8; k++) {
        wmma::fragment<wmma::matrix_a, 16, 16, 16, __half, wmma::row_major> a;
        wmma::load_matrix_sync(a, Xs + (warp * 16) * LDH + k * 16, LDH);
        #pragma unroll
        for (int n = 0; n < 8; n++) {
            wmma::fragment<wmma::matrix_b, 16, 16, 16, __half, wmma::row_major> b;
            wmma::load_matrix_sync(b, Ws + (k * 16) * LDH + n * 16, LDH);
            wmma::mma_sync(acc[n], a, b, acc[n]);
        }
    }
    __syncthreads();

    #pragma unroll
    for (int n = 0; n < 8; n++)
        wmma::store_matrix_sync(Os + (warp * 16) * GTILE + n * 16, acc[n], GTILE,
                                wmma::mem_row_major);
    __syncthreads();

    float4 bv = __ldg((const float4*)bias + lane);
    #pragma unroll
    for (int i = 0; i < 16; i++) {
        int r = warp * 16 + i;
        int gr = row0 + r;
        if (gr >= N_NODES) break;
        float4 v = *(const float4*)(Os + r * GTILE + lane * 4);
        v.x += bv.x; v.y += bv.y; v.z += bv.z; v.w += bv.w;
        if (z == 0) {
            v.x = (v.x >= 0.f) ? v.x : 0.2f * v.x;
            v.y = (v.y >= 0.f) ? v.y : 0.2f * v.y;
            v.z = (v.z >= 0.f) ? v.z : 0.2f * v.z;
            v.w = (v.w >= 0.f) ? v.w : 0.2f * v.w;
        } else {
            int deg = __ldg(rp + gr + 1) - __ldg(rp + gr);
            if (deg == 0) {
                v = make_float4(0.f, 0.f, 0.f, 0.f);
            } else {
                float ss = v.x*v.x + v.y*v.y + v.z*v.z + v.w*v.w;
                #pragma unroll
                for (int o = 16; o; o >>= 1) ss += __shfl_xor_sync(0xffffffffu, ss, o);
                float ns = fmaxf(sqrtf(ss), EPSF);
                float sc = (z == 1) ? (tanhf(ns) / ns) : (1.f / ns);
                v.x *= sc; v.y *= sc; v.z *= sc; v.w *= sc;
            }
        }
        __stcs((float4*)Y + (size_t)gr * 32 + lane, v);            // write-once stream
    }
}

// ---------------- launch --------------------------------------------------------
extern "C" void kernel_launch(void* const* d_in, const int* in_sizes, int n_in,
                              void* d_out, int out_size) {
    const float* e_emb = (const float*)d_in[0];
    const float* b_emb = (const float*)d_in[1];
    const float* s_emb = (const float*)d_in[2];
    const float* W_e   = (const float*)d_in[3];
    const float* b_e   = (const float*)d_in[4];
    const float* W_b   = (const float*)d_in[5];
    const float* b_b   = (const float*)d_in[6];
    const float* W_s   = (const float*)d_in[7];
    const float* b_s   = (const float*)d_in[8];
    const int*   src   = (const int*)d_in[9];
    const int*   dst   = (const int*)d_in[10];

    float* out = (float*)d_out;

    __half *pack, *emean, *bmean, *smean, *Wth;
    int *counts, *rowptr, *cursor, *csr;
    cudaGetSymbolAddress((void**)&pack,   g_pack);
    cudaGetSymbolAddress((void**)&emean,  g_emean);
    cudaGetSymbolAddress((void**)&bmean,  g_bmean);
    cudaGetSymbolAddress((void**)&smean,  g_smean);
    cudaGetSymbolAddress((void**)&Wth,    g_Wth);
    cudaGetSymbolAddress((void**)&counts, g_counts);
    cudaGetSymbolAddress((void**)&rowptr, g_rowptr);
    cudaGetSymbolAddress((void**)&cursor, g_cursor);
    cudaGetSymbolAddress((void**)&csr,    g_csr);
    int* status = counts + N_NODES;

    const int GSMEM = 2 * GTILE * LDH * 2;   // 69632 B
    cudaFuncSetAttribute(gemm_wmma3, cudaFuncAttributeMaxDynamicSharedMemorySize, GSMEM);

    // counts/status are zero at entry: zero-initialized at module load, then
    // re-zeroed inside scatter_pack_kernel every launch (graph-replay invariant).
    hist_kernel<<<2048, 256>>>((const int4*)dst, counts);
    scan_lookback<<<NBLK, 256>>>(counts, rowptr, cursor, status);
    scatter_pack_kernel<<<MERG_BLOCKS, 256>>>((const int4*)src, (const int4*)dst,
                                              cursor, csr,
                                              e_emb, b_emb, s_emb, pack,
                                              W_e, W_b, W_s, Wth, counts);

    // agg: 2-warp blocks for fine retirement granularity under degree imbalance
    agg_fused<<<(N_NODES * 32 + 63) / 64, 64>>>(pack, emean, bmean, smean, csr, rowptr);

    dim3 gg((N_NODES + GTILE - 1) / GTILE, 1, 3);   // 782 x 1 x 3
    gemm_wmma3<<<gg, 256, GSMEM>>>(emean, bmean, smean, Wth, b_e, b_b, b_s, out, rowptr);
}